// round 10
// baseline (speedup 1.0000x reference)
#include <cuda_runtime.h>
#include <cuda_bf16.h>
#include <cuda_fp16.h>
#include <cstdint>

#define NN  100000
#define EE  1600000
#define INF 256
#define HH  64
#define CC  16

// ---------------- scratch (no allocations allowed -> device globals) ----------------
__device__ float g_bufA[(size_t)NN * HH];   // holds fp16 h (12.8 MB)
__device__ float g_bufB[(size_t)NN * HH];   // holds fp16 h (12.8 MB)
__device__ float g_deg[NN];                 // weighted in-degree (excl. self loop)
__device__ float g_dinv[NN];
__device__ int   g_cnt[NN];
__device__ int   g_rowptr[NN + 1];
__device__ int   g_rank[EE];                // rank of edge within its dst bucket
__device__ uint2 g_edge[EE];                // packed (src, val) 8B
__device__ int   g_idx64;
__device__ int   g_blksum[128];
__device__ int   g_blkoff[128];
__device__ int   g_arrive;

// edge_index may be int64 (reference declares it) or int32 (jax x64-disabled
// canonicalization). Detected at runtime; branch on device flag.
__device__ __forceinline__ int ld_idx(const void* ei, long long pos) {
    if (g_idx64)
        return (int)((const long long*)ei)[pos];
    return ((const int*)ei)[pos];
}

// init: zero deg/cnt/arrive; thread 0 detects index width (odd 32-bit words of
// first 64 entries all zero iff int64, since indices < 1e5).
__global__ void k_init(const unsigned int* ei) {
    int i = blockIdx.x * blockDim.x + threadIdx.x;
    if (i < NN) { g_deg[i] = 0.0f; g_cnt[i] = 0; }
    if (i == 0) {
        unsigned v = 0;
        for (int j = 0; j < 64; j++) v |= ei[2 * j + 1];
        g_idx64 = (v == 0) ? 1 : 0;
        g_arrive = 0;
    }
}

// pass 1 over edges: weighted degree (no-return reduce) + count (return = rank)
__global__ void k_degcnt(const void* ei, const float* __restrict__ ew) {
    int e = blockIdx.x * blockDim.x + threadIdx.x;
    if (e < EE) {
        int d = ld_idx(ei, (long long)EE + e);       // dst row
        atomicAdd(&g_deg[d], ew[e]);                 // result unused -> RED
        g_rank[e] = atomicAdd(&g_cnt[d], 1);
    }
}

// ---- scan phase A: shuffle block scan; ticketed last block scans block sums ----
__global__ void k_scanA() {
    __shared__ int wsum[32];
    __shared__ int sb[128];
    __shared__ int s_last;
    const int t    = threadIdx.x;
    const int lane = t & 31;
    const int warp = t >> 5;
    int i = blockIdx.x * 1024 + t;
    int v = (i < NN) ? g_cnt[i] : 0;

    int x = v;
#pragma unroll
    for (int off = 1; off < 32; off <<= 1) {
        int y = __shfl_up_sync(0xffffffff, x, off);
        if (lane >= off) x += y;
    }
    if (lane == 31) wsum[warp] = x;
    __syncthreads();
    if (warp == 0) {
        int w = (lane < 32) ? wsum[lane] : 0;
#pragma unroll
        for (int off = 1; off < 32; off <<= 1) {
            int y = __shfl_up_sync(0xffffffff, w, off);
            if (lane >= off) w += y;
        }
        wsum[lane] = w;                              // inclusive warp sums
    }
    __syncthreads();
    int incl = x + (warp ? wsum[warp - 1] : 0);
    if (i < NN) g_rowptr[i] = incl - v;              // block-local exclusive
    if (t == 1023) g_blksum[blockIdx.x] = incl;
    __threadfence();
    __syncthreads();
    if (t == 0) s_last = (atomicAdd(&g_arrive, 1) == (int)gridDim.x - 1);
    __syncthreads();
    if (s_last) {                                    // uniform branch
        int nb = (int)gridDim.x;
        int bv = (t < 128 && t < nb) ? g_blksum[t] : 0;
        if (t < 128) sb[t] = bv;
        __syncthreads();
        for (int off = 1; off < 128; off <<= 1) {
            int a = (t < 128 && t >= off) ? sb[t - off] : 0;
            __syncthreads();
            if (t < 128) sb[t] += a;
            __syncthreads();
        }
        if (t < nb) g_blkoff[t] = sb[t] - bv;        // exclusive
    }
}

__global__ void k_scanC() {
    int i = blockIdx.x * blockDim.x + threadIdx.x;
    if (i < NN) {
        g_rowptr[i] = g_rowptr[i] + g_blkoff[i >> 10];
        g_dinv[i]   = rsqrtf(1.0f + g_deg[i]);       // +1 = self-loop weight
    }
    if (i == 0) g_rowptr[NN] = EE;
}

// pass 2 over edges: atomic-free placement via rowptr + rank, packed 8B store.
// stored val = dinv[src]*w  (dinv[dst] applied once per node in agg)
__global__ void k_scatter(const void* ei, const float* __restrict__ ew) {
    int e = blockIdx.x * blockDim.x + threadIdx.x;
    if (e < EE) {
        int s = ld_idx(ei, e);
        int d = ld_idx(ei, (long long)EE + e);
        int pos = g_rowptr[d] + g_rank[e];
        float v = g_dinv[s] * ew[e];
        g_edge[pos] = make_uint2((unsigned)s, __float_as_uint(v));
    }
}

// ================================ GEMM kernels ================================
#define APAD 72                               // 16-bit row stride (conflict-free frags)

// ---- GEMM1: fp32 A, bf16 hi/lo split (3 MMAs), fp16 out ----
#define SM_AHI 0
#define SM_ALO (128 * APAD)
#define SM_BHI (2 * 128 * APAD)
#define SM_BLO (2 * 128 * APAD + 64 * APAD)
#define SMEM_G1 ((2 * 128 * APAD + 2 * 64 * APAD) * 2)    // 55296 B

// ---- fused agg+GEMM: fp16 A in smem (exact), W hi/lo split ----
#define FA_BHI (128 * APAD)
#define FA_BLO (128 * APAD + 64 * APAD)
#define SMEM_FUSE ((128 * APAD + 2 * 64 * APAD) * 2)       // 36864 B
#define SMEM_FHEAD 37504                                   // head stage needs 37440

__device__ __forceinline__ void mma_bf16(float* c, const uint32_t* a,
                                         uint32_t b0, uint32_t b1) {
    asm volatile(
        "mma.sync.aligned.m16n8k16.row.col.f32.bf16.bf16.f32 "
        "{%0,%1,%2,%3}, {%4,%5,%6,%7}, {%8,%9}, {%0,%1,%2,%3};"
        : "+f"(c[0]), "+f"(c[1]), "+f"(c[2]), "+f"(c[3])
        : "r"(a[0]), "r"(a[1]), "r"(a[2]), "r"(a[3]), "r"(b0), "r"(b1));
}
__device__ __forceinline__ void mma_f16(float* c, const uint32_t* a,
                                        uint32_t b0, uint32_t b1) {
    asm volatile(
        "mma.sync.aligned.m16n8k16.row.col.f32.f16.f16.f32 "
        "{%0,%1,%2,%3}, {%4,%5,%6,%7}, {%8,%9}, {%0,%1,%2,%3};"
        : "+f"(c[0]), "+f"(c[1]), "+f"(c[2]), "+f"(c[3])
        : "r"(a[0]), "r"(a[1]), "r"(a[2]), "r"(a[3]), "r"(b0), "r"(b1));
}

// ---------------- GEMM1: bf16-split mainloop, fp32 A (128 threads) ----------------
template <int KTOT>
__device__ __forceinline__ void gemm_mainloop_bf16(
    const float* __restrict__ A, const float* __restrict__ W, int nrows,
    char* dsm, int row0, int tid, int wid, int g, int tg, float acc[2][8][4]) {
    __nv_bfloat16* Ahi = (__nv_bfloat16*)dsm + SM_AHI;
    __nv_bfloat16* Alo = (__nv_bfloat16*)dsm + SM_ALO;
    __nv_bfloat16* Bhi = (__nv_bfloat16*)dsm + SM_BHI;
    __nv_bfloat16* Blo = (__nv_bfloat16*)dsm + SM_BLO;
    const int m0 = wid * 32;

    for (int kt = 0; kt < KTOT; kt += 64) {
#pragma unroll
        for (int it = 0; it < 8; it++) {
            int chunk = it * 128 + tid;
            int r  = chunk >> 3;
            int kc = (chunk & 7) * 8;
            int row = row0 + r;
            float v[8];
            if (row < nrows) {
                const float4* p = (const float4*)(A + (size_t)row * KTOT + kt + kc);
                float4 a = p[0], b = p[1];
                v[0] = a.x; v[1] = a.y; v[2] = a.z; v[3] = a.w;
                v[4] = b.x; v[5] = b.y; v[6] = b.z; v[7] = b.w;
            } else {
#pragma unroll
                for (int j = 0; j < 8; j++) v[j] = 0.0f;
            }
#pragma unroll
            for (int j = 0; j < 4; j++) {
                __nv_bfloat162 h, l;
                h.x = __float2bfloat16(v[2 * j]);
                h.y = __float2bfloat16(v[2 * j + 1]);
                l.x = __float2bfloat16(v[2 * j]     - __bfloat162float(h.x));
                l.y = __float2bfloat16(v[2 * j + 1] - __bfloat162float(h.y));
                *(__nv_bfloat162*)&Ahi[r * APAD + kc + 2 * j] = h;
                *(__nv_bfloat162*)&Alo[r * APAD + kc + 2 * j] = l;
            }
        }
#pragma unroll
        for (int it = 0; it < 32; it++) {
            int idx = it * 128 + tid;
            int n = idx & 63, k = idx >> 6;
            float w = W[(size_t)(kt + k) * HH + n];
            __nv_bfloat16 h = __float2bfloat16(w);
            Bhi[n * APAD + k] = h;
            Blo[n * APAD + k] = __float2bfloat16(w - __bfloat162float(h));
        }
        __syncthreads();

#pragma unroll
        for (int kc = 0; kc < 64; kc += 16) {
            uint32_t ah[2][4], al[2][4];
#pragma unroll
            for (int mt = 0; mt < 2; mt++) {
                int r = m0 + mt * 16 + g;
                ah[mt][0] = *(const uint32_t*)&Ahi[r * APAD + kc + tg * 2];
                ah[mt][1] = *(const uint32_t*)&Ahi[(r + 8) * APAD + kc + tg * 2];
                ah[mt][2] = *(const uint32_t*)&Ahi[r * APAD + kc + 8 + tg * 2];
                ah[mt][3] = *(const uint32_t*)&Ahi[(r + 8) * APAD + kc + 8 + tg * 2];
                al[mt][0] = *(const uint32_t*)&Alo[r * APAD + kc + tg * 2];
                al[mt][1] = *(const uint32_t*)&Alo[(r + 8) * APAD + kc + tg * 2];
                al[mt][2] = *(const uint32_t*)&Alo[r * APAD + kc + 8 + tg * 2];
                al[mt][3] = *(const uint32_t*)&Alo[(r + 8) * APAD + kc + 8 + tg * 2];
            }
#pragma unroll
            for (int nt = 0; nt < 8; nt++) {
                int n = nt * 8 + g;
                uint32_t bh0 = *(const uint32_t*)&Bhi[n * APAD + kc + tg * 2];
                uint32_t bh1 = *(const uint32_t*)&Bhi[n * APAD + kc + 8 + tg * 2];
                uint32_t bl0 = *(const uint32_t*)&Blo[n * APAD + kc + tg * 2];
                uint32_t bl1 = *(const uint32_t*)&Blo[n * APAD + kc + 8 + tg * 2];
#pragma unroll
                for (int mt = 0; mt < 2; mt++) {
                    mma_bf16(acc[mt][nt], ah[mt], bh0, bh1);   // hi*hi
                    mma_bf16(acc[mt][nt], ah[mt], bl0, bl1);   // hi*lo
                    mma_bf16(acc[mt][nt], al[mt], bh0, bh1);   // lo*hi
                }
            }
        }
        __syncthreads();
    }
}

// GEMM1: x(fp32) @ W1 -> fp16 h
template <int KTOT>
__global__ void __launch_bounds__(128)
gemm_tc(const float* __restrict__ A, const float* __restrict__ W,
        __half2* __restrict__ out, int nrows) {
    extern __shared__ char dsm[];
    const int tid = threadIdx.x, wid = tid >> 5, lane = tid & 31;
    const int g = lane >> 2, tg = lane & 3;
    const int row0 = blockIdx.x * 128;
    float acc[2][8][4];
#pragma unroll
    for (int mt = 0; mt < 2; mt++)
#pragma unroll
        for (int nt = 0; nt < 8; nt++)
#pragma unroll
            for (int j = 0; j < 4; j++) acc[mt][nt][j] = 0.0f;
    gemm_mainloop_bf16<KTOT>(A, W, nrows, dsm, row0, tid, wid, g, tg, acc);
#pragma unroll
    for (int mt = 0; mt < 2; mt++) {
        int r0 = row0 + wid * 32 + mt * 16 + g;
        int r1 = r0 + 8;
#pragma unroll
        for (int nt = 0; nt < 8; nt++) {
            int h2c = nt * 4 + tg;
            if (r0 < nrows)
                out[(size_t)r0 * 32 + h2c] = __floats2half2_rn(acc[mt][nt][0], acc[mt][nt][1]);
            if (r1 < nrows)
                out[(size_t)r1 * 32 + h2c] = __floats2half2_rn(acc[mt][nt][2], acc[mt][nt][3]);
        }
    }
}

// ---------------- fused building blocks (256-thread CTAs) ----------------

// phase 1: 16 half-warps aggregate 128 nodes into smem A-tile (fp16, relu'd)
// Ah[rl][f] = relu( dinv * (dinv*h[n] + sum val'*h[src]) + bias )
__device__ __forceinline__ void agg_phase(const uint2* __restrict__ hp,
                                          const float* __restrict__ bias,
                                          __half* Ah, int row0, int tid) {
    const int hw = tid >> 4;                   // 0..15
    const int l  = tid & 15;                   // feats 4l..4l+3
    const float4 bv = *(const float4*)&bias[4 * l];
#pragma unroll 1
    for (int round = 0; round < 8; round++) {
        int rl = round * 16 + hw;              // local row 0..127
        int w  = row0 + rl;
        uint2 o = make_uint2(0u, 0u);
        if (w < NN) {
            float di = g_dinv[w];
            uint2 hv = hp[(size_t)w * 16 + l];
            float2 h0 = __half22float2(*(const __half2*)&hv.x);
            float2 h1 = __half22float2(*(const __half2*)&hv.y);
            float a0 = di * h0.x, a1 = di * h0.y, a2 = di * h1.x, a3 = di * h1.y;
            int e  = __ldg(&g_rowptr[w]);
            int e1 = __ldg(&g_rowptr[w + 1]);
            for (; e + 4 <= e1; e += 4) {
                uint2 ev0 = g_edge[e],     ev1 = g_edge[e + 1];
                uint2 ev2 = g_edge[e + 2], ev3 = g_edge[e + 3];
                uint2 p0 = hp[(size_t)ev0.x * 16 + l];
                uint2 p1 = hp[(size_t)ev1.x * 16 + l];
                uint2 p2 = hp[(size_t)ev2.x * 16 + l];
                uint2 p3 = hp[(size_t)ev3.x * 16 + l];
                float v0 = __uint_as_float(ev0.y), v1 = __uint_as_float(ev1.y);
                float v2 = __uint_as_float(ev2.y), v3 = __uint_as_float(ev3.y);
                float2 q;
                q = __half22float2(*(const __half2*)&p0.x); a0 += v0 * q.x; a1 += v0 * q.y;
                q = __half22float2(*(const __half2*)&p0.y); a2 += v0 * q.x; a3 += v0 * q.y;
                q = __half22float2(*(const __half2*)&p1.x); a0 += v1 * q.x; a1 += v1 * q.y;
                q = __half22float2(*(const __half2*)&p1.y); a2 += v1 * q.x; a3 += v1 * q.y;
                q = __half22float2(*(const __half2*)&p2.x); a0 += v2 * q.x; a1 += v2 * q.y;
                q = __half22float2(*(const __half2*)&p2.y); a2 += v2 * q.x; a3 += v2 * q.y;
                q = __half22float2(*(const __half2*)&p3.x); a0 += v3 * q.x; a1 += v3 * q.y;
                q = __half22float2(*(const __half2*)&p3.y); a2 += v3 * q.x; a3 += v3 * q.y;
            }
            for (; e < e1; e++) {
                uint2 ev = g_edge[e];
                uint2 p  = hp[(size_t)ev.x * 16 + l];
                float v  = __uint_as_float(ev.y);
                float2 q;
                q = __half22float2(*(const __half2*)&p.x); a0 += v * q.x; a1 += v * q.y;
                q = __half22float2(*(const __half2*)&p.y); a2 += v * q.x; a3 += v * q.y;
            }
            __half2 o0 = __floats2half2_rn(fmaxf(di * a0 + bv.x, 0.0f),
                                           fmaxf(di * a1 + bv.y, 0.0f));
            __half2 o1 = __floats2half2_rn(fmaxf(di * a2 + bv.z, 0.0f),
                                           fmaxf(di * a3 + bv.w, 0.0f));
            o = make_uint2(*(uint32_t*)&o0, *(uint32_t*)&o1);
        }
        *(uint2*)&Ah[rl * APAD + 4 * l] = o;
    }
}

// load W[64][64] fp32 -> smem hi/lo fp16 split (256 threads)
__device__ __forceinline__ void load_Wsplit(const float* __restrict__ W,
                                            __half* Bhi, __half* Blo, int tid) {
#pragma unroll
    for (int it = 0; it < 16; it++) {
        int idx = it * 256 + tid;
        int n = idx & 63, k = idx >> 6;
        float w = W[(size_t)k * HH + n];
        __half h = __float2half_rn(w);
        Bhi[n * APAD + k] = h;
        Blo[n * APAD + k] = __float2half_rn(w - __half2float(h));
    }
}

// phase 2: warp wid computes rows [wid*16, wid*16+16) x 64, acc[8][4]
__device__ __forceinline__ void mma_phase(const __half* Ah, const __half* Bhi,
                                          const __half* Blo, int wid, int g, int tg,
                                          float acc[8][4]) {
    const int m0 = wid * 16;
#pragma unroll
    for (int kc = 0; kc < 64; kc += 16) {
        uint32_t a[4];
        int r = m0 + g;
        a[0] = *(const uint32_t*)&Ah[r * APAD + kc + tg * 2];
        a[1] = *(const uint32_t*)&Ah[(r + 8) * APAD + kc + tg * 2];
        a[2] = *(const uint32_t*)&Ah[r * APAD + kc + 8 + tg * 2];
        a[3] = *(const uint32_t*)&Ah[(r + 8) * APAD + kc + 8 + tg * 2];
#pragma unroll
        for (int nt = 0; nt < 8; nt++) {
            int n = nt * 8 + g;
            uint32_t bh0 = *(const uint32_t*)&Bhi[n * APAD + kc + tg * 2];
            uint32_t bh1 = *(const uint32_t*)&Bhi[n * APAD + kc + 8 + tg * 2];
            uint32_t bl0 = *(const uint32_t*)&Blo[n * APAD + kc + tg * 2];
            uint32_t bl1 = *(const uint32_t*)&Blo[n * APAD + kc + 8 + tg * 2];
            mma_f16(acc[nt], a, bh0, bh1);     // A*Whi
            mma_f16(acc[nt], a, bl0, bl1);     // A*Wlo
        }
    }
}

// fused: h2 = agg(h1) @ W2   (agg bias/relu folded into phase 1)
__global__ void __launch_bounds__(256)
fused_agg_gemm(const uint2* __restrict__ hp, const float* __restrict__ bias,
               const float* __restrict__ W, __half2* __restrict__ out, int nrows) {
    extern __shared__ char dsm[];
    __half* Ah  = (__half*)dsm;
    __half* Bhi = (__half*)dsm + FA_BHI;
    __half* Blo = (__half*)dsm + FA_BLO;
    const int tid = threadIdx.x, wid = tid >> 5, lane = tid & 31;
    const int g = lane >> 2, tg = lane & 3;
    const int row0 = blockIdx.x * 128;

    load_Wsplit(W, Bhi, Blo, tid);
    agg_phase(hp, bias, Ah, row0, tid);
    __syncthreads();

    float acc[8][4];
#pragma unroll
    for (int nt = 0; nt < 8; nt++)
#pragma unroll
        for (int j = 0; j < 4; j++) acc[nt][j] = 0.0f;
    mma_phase(Ah, Bhi, Blo, wid, g, tg, acc);

    int r0 = row0 + wid * 16 + g;
    int r1 = r0 + 8;
#pragma unroll
    for (int nt = 0; nt < 8; nt++) {
        int h2c = nt * 4 + tg;
        if (r0 < nrows)
            out[(size_t)r0 * 32 + h2c] = __floats2half2_rn(acc[nt][0], acc[nt][1]);
        if (r1 < nrows)
            out[(size_t)r1 * 32 + h2c] = __floats2half2_rn(acc[nt][2], acc[nt][3]);
    }
}

// fused: out = softmax( relu( agg(h2) @ Wm1 + bm1 ) @ Wm2 + bm2 )
__global__ void __launch_bounds__(256)
fused_agg_head(const uint2* __restrict__ hp, const float* __restrict__ bias_agg,
               const float* __restrict__ Wm1, const float* __restrict__ bm1,
               const float* __restrict__ Wm2, const float* __restrict__ bm2,
               float* __restrict__ out, int nrows) {
    extern __shared__ char dsm[];
    __half* Ah  = (__half*)dsm;
    __half* Bhi = (__half*)dsm + FA_BHI;
    __half* Blo = (__half*)dsm + FA_BLO;
    const int tid = threadIdx.x, wid = tid >> 5, lane = tid & 31;
    const int g = lane >> 2, tg = lane & 3;
    const int row0 = blockIdx.x * 128;

    load_Wsplit(Wm1, Bhi, Blo, tid);
    agg_phase(hp, bias_agg, Ah, row0, tid);
    __syncthreads();

    float acc[8][4];
#pragma unroll
    for (int nt = 0; nt < 8; nt++)
#pragma unroll
        for (int j = 0; j < 4; j++) acc[nt][j] = 0.0f;
    mma_phase(Ah, Bhi, Blo, wid, g, tg, acc);
    __syncthreads();                           // all warps done reading tiles

    // stage relu(acc + bm1) into smem [128][65] (tile memory now dead)
    float* st  = (float*)dsm;                  // 33280 B
    float* sW  = st + 128 * 65;                // 4096 B
    float* sbv = sW + 64 * 16;                 // 64 B (total 37440 <= SMEM_FHEAD)
    {
        int rl0 = wid * 16 + g;
#pragma unroll
        for (int nt = 0; nt < 8; nt++) {
            int c = nt * 8 + tg * 2;
            float b0 = __ldg(&bm1[c]), b1 = __ldg(&bm1[c + 1]);
            st[rl0 * 65 + c]           = fmaxf(acc[nt][0] + b0, 0.0f);
            st[rl0 * 65 + c + 1]       = fmaxf(acc[nt][1] + b1, 0.0f);
            st[(rl0 + 8) * 65 + c]     = fmaxf(acc[nt][2] + b0, 0.0f);
            st[(rl0 + 8) * 65 + c + 1] = fmaxf(acc[nt][3] + b1, 0.0f);
        }
    }
    for (int i = tid; i < HH * CC; i += 256) sW[i] = Wm2[i];
    if (tid < CC) sbv[tid] = bm2[tid];
    __syncthreads();

    if (tid < 128) {
        int r = row0 + tid;                    // one row per thread
        if (r < nrows) {
            float lg[CC];
#pragma unroll
            for (int c = 0; c < CC; c++) lg[c] = sbv[c];
            const float* mrow = st + tid * 65; // stride 65 -> conflict-free
#pragma unroll
            for (int k = 0; k < HH; k++) {
                float av = mrow[k];
#pragma unroll
                for (int c = 0; c < CC; c++) lg[c] += av * sW[k * CC + c];
            }
            float mx = lg[0];
#pragma unroll
            for (int c = 1; c < CC; c++) mx = fmaxf(mx, lg[c]);
            float ssum = 0.0f;
#pragma unroll
            for (int c = 0; c < CC; c++) { lg[c] = __expf(lg[c] - mx); ssum += lg[c]; }
            float inv = 1.0f / ssum;
            float4* op = (float4*)(out + (size_t)r * CC);
#pragma unroll
            for (int c4 = 0; c4 < 4; c4++)
                op[c4] = make_float4(lg[c4 * 4] * inv, lg[c4 * 4 + 1] * inv,
                                     lg[c4 * 4 + 2] * inv, lg[c4 * 4 + 3] * inv);
        }
    }
}

// ---------------- launch ----------------
extern "C" void kernel_launch(void* const* d_in, const int* in_sizes, int n_in,
                              void* d_out, int out_size) {
    const float* x   = (const float*)d_in[0];
    const void*  ei  = d_in[1];
    const float* ew  = (const float*)d_in[2];
    const float* W1  = (const float*)d_in[3];
    const float* b1  = (const float*)d_in[4];
    const float* W2  = (const float*)d_in[5];
    const float* b2  = (const float*)d_in[6];
    const float* Wm1 = (const float*)d_in[7];
    const float* bm1 = (const float*)d_in[8];
    const float* Wm2 = (const float*)d_in[9];
    const float* bm2 = (const float*)d_in[10];
    float* out = (float*)d_out;

    float *pA, *pB;
    cudaGetSymbolAddress((void**)&pA, g_bufA);
    cudaGetSymbolAddress((void**)&pB, g_bufB);
    __half2* pA16 = (__half2*)pA;
    __half2* pB16 = (__half2*)pB;

    static cudaStream_t s2 = 0;
    static cudaEvent_t evA = 0, evB = 0;
    if (!s2) {
        cudaStreamCreateWithFlags(&s2, cudaStreamNonBlocking);
        cudaEventCreateWithFlags(&evA, cudaEventDisableTiming);
        cudaEventCreateWithFlags(&evB, cudaEventDisableTiming);
        cudaFuncSetAttribute(gemm_tc<INF>,  cudaFuncAttributeMaxDynamicSharedMemorySize, SMEM_G1);
        cudaFuncSetAttribute(fused_agg_gemm, cudaFuncAttributeMaxDynamicSharedMemorySize, SMEM_FUSE);
        cudaFuncSetAttribute(fused_agg_head, cudaFuncAttributeMaxDynamicSharedMemorySize, SMEM_FHEAD);
    }

    const int gemm_grid = (NN + 127) / 128;              // 782
    const int nblk      = (NN + 1023) / 1024;            // 98

    // fork: GEMM1 (x @ W1 -> fp16 h) alongside CSR build
    cudaEventRecord(evA, 0);
    cudaStreamWaitEvent(s2, evA, 0);
    gemm_tc<INF><<<gemm_grid, 128, SMEM_G1, s2>>>(x, W1, pA16, NN);
    cudaEventRecord(evB, s2);

    // CSR build on main stream
    k_init<<<(NN + 255) / 256, 256>>>((const unsigned int*)ei);
    k_degcnt<<<(EE + 255) / 256, 256>>>(ei, ew);
    k_scanA<<<nblk, 1024>>>();
    k_scanC<<<(NN + 255) / 256, 256>>>();
    k_scatter<<<(EE + 255) / 256, 256>>>(ei, ew);

    cudaStreamWaitEvent(0, evB, 0);                      // join GEMM1

    // conv1+relu fused into GEMM2; conv2+relu fused into MLP head
    fused_agg_gemm<<<gemm_grid, 256, SMEM_FUSE>>>((const uint2*)pA16, b1, W2, pB16, NN);
    fused_agg_head<<<gemm_grid, 256, SMEM_FHEAD>>>((const uint2*)pB16, b2, Wm1, bm1,
                                                   Wm2, bm2, out, NN);
}

// round 11
// speedup vs baseline: 1.2098x; 1.2098x over previous
#include <cuda_runtime.h>
#include <cuda_bf16.h>
#include <cuda_fp16.h>
#include <cstdint>

#define NN  100000
#define EE  1600000
#define INF 256
#define HH  64
#define CC  16

#define FIXSCALE 33554432.0f                 // 2^25
#define CNTSHIFT 40

// ---------------- scratch (no allocations allowed -> device globals) ----------------
__device__ float g_bufA[(size_t)NN * HH];   // holds fp16 h (12.8 MB)
__device__ float g_bufB[(size_t)NN * HH];   // holds fp16 h (12.8 MB)
__device__ unsigned long long g_degcnt[NN]; // packed: cnt<<40 | deg_fixed(2^-25)
__device__ float g_dinv[NN];
__device__ int   g_rowptr[NN + 1];
__device__ int   g_rank[EE];                // rank of edge within its dst bucket
__device__ uint2 g_edge[EE];                // packed (src, val) 8B
__device__ int   g_idx64;
__device__ int   g_blksum[128];
__device__ int   g_blkoff[128];
__device__ int   g_arrive;

// edge_index may be int64 (reference declares it) or int32 (jax x64-disabled
// canonicalization). Detected at runtime; branch on device flag.
__device__ __forceinline__ int ld_idx(const void* ei, long long pos) {
    if (g_idx64)
        return (int)((const long long*)ei)[pos];
    return ((const int*)ei)[pos];
}

// init: zero degcnt/arrive; thread 0 detects index width (odd 32-bit words of
// first 64 entries all zero iff int64, since indices < 1e5).
__global__ void k_init(const unsigned int* ei) {
    int i = blockIdx.x * blockDim.x + threadIdx.x;
    if (i < NN) g_degcnt[i] = 0ull;
    if (i == 0) {
        unsigned v = 0;
        for (int j = 0; j < 64; j++) v |= ei[2 * j + 1];
        g_idx64 = (v == 0) ? 1 : 0;
        g_arrive = 0;
    }
}

// pass 1 over edges: ONE packed 64-bit atomic per edge.
// add = (1 << 40) | round(ew * 2^25); return's high bits = rank in dst bucket.
__global__ void k_degcnt(const void* ei, const float* __restrict__ ew) {
    int e = blockIdx.x * blockDim.x + threadIdx.x;
    if (e < EE) {
        int d = ld_idx(ei, (long long)EE + e);       // dst row
        unsigned long long add =
            (1ull << CNTSHIFT) |
            (unsigned long long)(unsigned)__float2uint_rn(ew[e] * FIXSCALE);
        unsigned long long old = atomicAdd(&g_degcnt[d], add);
        g_rank[e] = (int)(old >> CNTSHIFT);
    }
}

// ---- scan phase A: shuffle block scan; ticketed last block scans block sums ----
__global__ void k_scanA() {
    __shared__ int wsum[32];
    __shared__ int sb[128];
    __shared__ int s_last;
    const int t    = threadIdx.x;
    const int lane = t & 31;
    const int warp = t >> 5;
    int i = blockIdx.x * 1024 + t;
    int v = (i < NN) ? (int)(g_degcnt[i] >> CNTSHIFT) : 0;

    int x = v;
#pragma unroll
    for (int off = 1; off < 32; off <<= 1) {
        int y = __shfl_up_sync(0xffffffff, x, off);
        if (lane >= off) x += y;
    }
    if (lane == 31) wsum[warp] = x;
    __syncthreads();
    if (warp == 0) {
        int w = (lane < 32) ? wsum[lane] : 0;
#pragma unroll
        for (int off = 1; off < 32; off <<= 1) {
            int y = __shfl_up_sync(0xffffffff, w, off);
            if (lane >= off) w += y;
        }
        wsum[lane] = w;                              // inclusive warp sums
    }
    __syncthreads();
    int incl = x + (warp ? wsum[warp - 1] : 0);
    if (i < NN) g_rowptr[i] = incl - v;              // block-local exclusive
    if (t == 1023) g_blksum[blockIdx.x] = incl;
    __threadfence();
    __syncthreads();
    if (t == 0) s_last = (atomicAdd(&g_arrive, 1) == (int)gridDim.x - 1);
    __syncthreads();
    if (s_last) {                                    // uniform branch
        int nb = (int)gridDim.x;
        int bv = (t < 128 && t < nb) ? g_blksum[t] : 0;
        if (t < 128) sb[t] = bv;
        __syncthreads();
        for (int off = 1; off < 128; off <<= 1) {
            int a = (t < 128 && t >= off) ? sb[t - off] : 0;
            __syncthreads();
            if (t < 128) sb[t] += a;
            __syncthreads();
        }
        if (t < nb) g_blkoff[t] = sb[t] - bv;        // exclusive
    }
}

__global__ void k_scanC() {
    int i = blockIdx.x * blockDim.x + threadIdx.x;
    if (i < NN) {
        g_rowptr[i] = g_rowptr[i] + g_blkoff[i >> 10];
        unsigned long long dc = g_degcnt[i];
        float deg = (float)((double)(dc & ((1ull << CNTSHIFT) - 1)) *
                            (1.0 / (double)FIXSCALE));
        g_dinv[i] = rsqrtf(1.0f + deg);              // +1 = self-loop weight
    }
    if (i == 0) g_rowptr[NN] = EE;
}

// pass 2 over edges: atomic-free placement via rowptr + rank, packed 8B store.
// stored val = dinv[src]*w  (dinv[dst] applied once per node in agg)
__global__ void k_scatter(const void* ei, const float* __restrict__ ew) {
    int e = blockIdx.x * blockDim.x + threadIdx.x;
    if (e < EE) {
        int s = ld_idx(ei, e);
        int d = ld_idx(ei, (long long)EE + e);
        int pos = g_rowptr[d] + g_rank[e];
        float v = g_dinv[s] * ew[e];
        g_edge[pos] = make_uint2((unsigned)s, __float_as_uint(v));
    }
}

// ================================ GEMM kernels ================================
#define APAD 72                               // 16-bit row stride (conflict-free frags)

// ---- GEMM1: fp32 A, bf16 hi/lo split (3 MMAs), fp16 out ----
#define SM_AHI 0
#define SM_ALO (128 * APAD)
#define SM_BHI (2 * 128 * APAD)
#define SM_BLO (2 * 128 * APAD + 64 * APAD)
#define SMEM_DYN ((2 * 128 * APAD + 2 * 64 * APAD) * 2)   // 55296 B

// ---- GEMM2/head: fp16 A exact (2 MMAs), W hi/lo split ----
#define SMF_A   0
#define SMF_BHI (128 * APAD)
#define SMF_BLO (128 * APAD + 64 * APAD)
#define SMEM_F16 ((128 * APAD + 2 * 64 * APAD) * 2)        // 36864 B
#define SMEM_HEAD 37504                                    // head stage needs 37440

__device__ __forceinline__ void mma_bf16(float* c, const uint32_t* a,
                                         uint32_t b0, uint32_t b1) {
    asm volatile(
        "mma.sync.aligned.m16n8k16.row.col.f32.bf16.bf16.f32 "
        "{%0,%1,%2,%3}, {%4,%5,%6,%7}, {%8,%9}, {%0,%1,%2,%3};"
        : "+f"(c[0]), "+f"(c[1]), "+f"(c[2]), "+f"(c[3])
        : "r"(a[0]), "r"(a[1]), "r"(a[2]), "r"(a[3]), "r"(b0), "r"(b1));
}
__device__ __forceinline__ void mma_f16(float* c, const uint32_t* a,
                                        uint32_t b0, uint32_t b1) {
    asm volatile(
        "mma.sync.aligned.m16n8k16.row.col.f32.f16.f16.f32 "
        "{%0,%1,%2,%3}, {%4,%5,%6,%7}, {%8,%9}, {%0,%1,%2,%3};"
        : "+f"(c[0]), "+f"(c[1]), "+f"(c[2]), "+f"(c[3])
        : "r"(a[0]), "r"(a[1]), "r"(a[2]), "r"(a[3]), "r"(b0), "r"(b1));
}

// bf16-split mainloop (GEMM1), fp32 A
template <int KTOT>
__device__ __forceinline__ void gemm_mainloop_bf16(
    const float* __restrict__ A, const float* __restrict__ W, int nrows,
    char* dsm, int row0, int tid, int wid, int g, int tg, float acc[2][8][4]) {
    __nv_bfloat16* Ahi = (__nv_bfloat16*)dsm + SM_AHI;
    __nv_bfloat16* Alo = (__nv_bfloat16*)dsm + SM_ALO;
    __nv_bfloat16* Bhi = (__nv_bfloat16*)dsm + SM_BHI;
    __nv_bfloat16* Blo = (__nv_bfloat16*)dsm + SM_BLO;
    const int m0 = wid * 32;

    for (int kt = 0; kt < KTOT; kt += 64) {
#pragma unroll
        for (int it = 0; it < 8; it++) {
            int chunk = it * 128 + tid;
            int r  = chunk >> 3;
            int kc = (chunk & 7) * 8;
            int row = row0 + r;
            float v[8];
            if (row < nrows) {
                const float4* p = (const float4*)(A + (size_t)row * KTOT + kt + kc);
                float4 a = p[0], b = p[1];
                v[0] = a.x; v[1] = a.y; v[2] = a.z; v[3] = a.w;
                v[4] = b.x; v[5] = b.y; v[6] = b.z; v[7] = b.w;
            } else {
#pragma unroll
                for (int j = 0; j < 8; j++) v[j] = 0.0f;
            }
#pragma unroll
            for (int j = 0; j < 4; j++) {
                __nv_bfloat162 h, l;
                h.x = __float2bfloat16(v[2 * j]);
                h.y = __float2bfloat16(v[2 * j + 1]);
                l.x = __float2bfloat16(v[2 * j]     - __bfloat162float(h.x));
                l.y = __float2bfloat16(v[2 * j + 1] - __bfloat162float(h.y));
                *(__nv_bfloat162*)&Ahi[r * APAD + kc + 2 * j] = h;
                *(__nv_bfloat162*)&Alo[r * APAD + kc + 2 * j] = l;
            }
        }
#pragma unroll
        for (int it = 0; it < 32; it++) {
            int idx = it * 128 + tid;
            int n = idx & 63, k = idx >> 6;
            float w = W[(size_t)(kt + k) * HH + n];
            __nv_bfloat16 h = __float2bfloat16(w);
            Bhi[n * APAD + k] = h;
            Blo[n * APAD + k] = __float2bfloat16(w - __bfloat162float(h));
        }
        __syncthreads();

#pragma unroll
        for (int kc = 0; kc < 64; kc += 16) {
            uint32_t ah[2][4], al[2][4];
#pragma unroll
            for (int mt = 0; mt < 2; mt++) {
                int r = m0 + mt * 16 + g;
                ah[mt][0] = *(const uint32_t*)&Ahi[r * APAD + kc + tg * 2];
                ah[mt][1] = *(const uint32_t*)&Ahi[(r + 8) * APAD + kc + tg * 2];
                ah[mt][2] = *(const uint32_t*)&Ahi[r * APAD + kc + 8 + tg * 2];
                ah[mt][3] = *(const uint32_t*)&Ahi[(r + 8) * APAD + kc + 8 + tg * 2];
                al[mt][0] = *(const uint32_t*)&Alo[r * APAD + kc + tg * 2];
                al[mt][1] = *(const uint32_t*)&Alo[(r + 8) * APAD + kc + tg * 2];
                al[mt][2] = *(const uint32_t*)&Alo[r * APAD + kc + 8 + tg * 2];
                al[mt][3] = *(const uint32_t*)&Alo[(r + 8) * APAD + kc + 8 + tg * 2];
            }
#pragma unroll
            for (int nt = 0; nt < 8; nt++) {
                int n = nt * 8 + g;
                uint32_t bh0 = *(const uint32_t*)&Bhi[n * APAD + kc + tg * 2];
                uint32_t bh1 = *(const uint32_t*)&Bhi[n * APAD + kc + 8 + tg * 2];
                uint32_t bl0 = *(const uint32_t*)&Blo[n * APAD + kc + tg * 2];
                uint32_t bl1 = *(const uint32_t*)&Blo[n * APAD + kc + 8 + tg * 2];
#pragma unroll
                for (int mt = 0; mt < 2; mt++) {
                    mma_bf16(acc[mt][nt], ah[mt], bh0, bh1);   // hi*hi
                    mma_bf16(acc[mt][nt], ah[mt], bl0, bl1);   // hi*lo
                    mma_bf16(acc[mt][nt], al[mt], bh0, bh1);   // lo*hi
                }
            }
        }
        __syncthreads();
    }
}

// fp16-exact-A mainloop (K=64): A from fp16 table, W split hi/lo (2 MMAs)
__device__ __forceinline__ void gemm_mainloop_f16(
    const uint2* __restrict__ A16, const float* __restrict__ W, int nrows,
    char* dsm, int row0, int tid, int wid, int g, int tg, float acc[2][8][4]) {
    __half* Ah  = (__half*)dsm + SMF_A;
    __half* Bhi = (__half*)dsm + SMF_BHI;
    __half* Blo = (__half*)dsm + SMF_BLO;
    const int m0 = wid * 32;

#pragma unroll
    for (int it = 0; it < 16; it++) {                // A: 128 rows x 64 fp16
        int idx = it * 128 + tid;
        int r = idx >> 4, c = idx & 15;              // c = 8B chunk (4 halfs)
        int row = row0 + r;
        uint2 v = (row < nrows) ? A16[(size_t)row * 16 + c] : make_uint2(0u, 0u);
        *(uint2*)&Ah[r * APAD + c * 4] = v;
    }
#pragma unroll
    for (int it = 0; it < 32; it++) {                // B: W[k][n] -> Bs[n][k]
        int idx = it * 128 + tid;
        int n = idx & 63, k = idx >> 6;
        float w = W[(size_t)k * HH + n];
        __half h = __float2half_rn(w);
        Bhi[n * APAD + k] = h;
        Blo[n * APAD + k] = __float2half_rn(w - __half2float(h));
    }
    __syncthreads();

#pragma unroll
    for (int kc = 0; kc < 64; kc += 16) {
        uint32_t a[2][4];
#pragma unroll
        for (int mt = 0; mt < 2; mt++) {
            int r = m0 + mt * 16 + g;
            a[mt][0] = *(const uint32_t*)&Ah[r * APAD + kc + tg * 2];
            a[mt][1] = *(const uint32_t*)&Ah[(r + 8) * APAD + kc + tg * 2];
            a[mt][2] = *(const uint32_t*)&Ah[r * APAD + kc + 8 + tg * 2];
            a[mt][3] = *(const uint32_t*)&Ah[(r + 8) * APAD + kc + 8 + tg * 2];
        }
#pragma unroll
        for (int nt = 0; nt < 8; nt++) {
            int n = nt * 8 + g;
            uint32_t bh0 = *(const uint32_t*)&Bhi[n * APAD + kc + tg * 2];
            uint32_t bh1 = *(const uint32_t*)&Bhi[n * APAD + kc + 8 + tg * 2];
            uint32_t bl0 = *(const uint32_t*)&Blo[n * APAD + kc + tg * 2];
            uint32_t bl1 = *(const uint32_t*)&Blo[n * APAD + kc + 8 + tg * 2];
#pragma unroll
            for (int mt = 0; mt < 2; mt++) {
                mma_f16(acc[mt][nt], a[mt], bh0, bh1);   // A*Whi
                mma_f16(acc[mt][nt], a[mt], bl0, bl1);   // A*Wlo
            }
        }
    }
    __syncthreads();                                 // smem reusable after this
}

// fp16 epilogue writer (h layout: row * 32 half2, feature-linear)
__device__ __forceinline__ void write_h16(__half2* out, int nrows, int row0,
                                          int wid, int g, int tg, float acc[2][8][4]) {
#pragma unroll
    for (int mt = 0; mt < 2; mt++) {
        int r0 = row0 + wid * 32 + mt * 16 + g;
        int r1 = r0 + 8;
#pragma unroll
        for (int nt = 0; nt < 8; nt++) {
            int h2c = nt * 4 + tg;
            if (r0 < nrows)
                out[(size_t)r0 * 32 + h2c] = __floats2half2_rn(acc[mt][nt][0], acc[mt][nt][1]);
            if (r1 < nrows)
                out[(size_t)r1 * 32 + h2c] = __floats2half2_rn(acc[mt][nt][2], acc[mt][nt][3]);
        }
    }
}

// GEMM1: x(fp32) @ W1 -> fp16 h
template <int KTOT>
__global__ void __launch_bounds__(128)
gemm_tc(const float* __restrict__ A, const float* __restrict__ W,
        __half2* __restrict__ out, int nrows) {
    extern __shared__ char dsm[];
    const int tid = threadIdx.x, wid = tid >> 5, lane = tid & 31;
    const int g = lane >> 2, tg = lane & 3;
    const int row0 = blockIdx.x * 128;
    float acc[2][8][4];
#pragma unroll
    for (int mt = 0; mt < 2; mt++)
#pragma unroll
        for (int nt = 0; nt < 8; nt++)
#pragma unroll
            for (int j = 0; j < 4; j++) acc[mt][nt][j] = 0.0f;
    gemm_mainloop_bf16<KTOT>(A, W, nrows, dsm, row0, tid, wid, g, tg, acc);
    write_h16(out, nrows, row0, wid, g, tg, acc);
}

// GEMM2: h(fp16) @ W2 -> fp16 h
__global__ void __launch_bounds__(128)
gemm_f16(const uint2* __restrict__ A16, const float* __restrict__ W,
         __half2* __restrict__ out, int nrows) {
    extern __shared__ char dsm[];
    const int tid = threadIdx.x, wid = tid >> 5, lane = tid & 31;
    const int g = lane >> 2, tg = lane & 3;
    const int row0 = blockIdx.x * 128;
    float acc[2][8][4];
#pragma unroll
    for (int mt = 0; mt < 2; mt++)
#pragma unroll
        for (int nt = 0; nt < 8; nt++)
#pragma unroll
            for (int j = 0; j < 4; j++) acc[mt][nt][j] = 0.0f;
    gemm_mainloop_f16(A16, W, nrows, dsm, row0, tid, wid, g, tg, acc);
    write_h16(out, nrows, row0, wid, g, tg, acc);
}

// GEMM3 (fp16 A) + bias/relu + fused MLP head (logits @ Wm2 + bm2, softmax)
__global__ void __launch_bounds__(128)
gemm_head(const uint2* __restrict__ A16, const float* __restrict__ Wm1,
          const float* __restrict__ bm1, const float* __restrict__ Wm2,
          const float* __restrict__ bm2, float* __restrict__ out, int nrows) {
    extern __shared__ char dsm[];
    const int tid = threadIdx.x, wid = tid >> 5, lane = tid & 31;
    const int g = lane >> 2, tg = lane & 3;
    const int row0 = blockIdx.x * 128;
    float acc[2][8][4];
#pragma unroll
    for (int mt = 0; mt < 2; mt++)
#pragma unroll
        for (int nt = 0; nt < 8; nt++)
#pragma unroll
            for (int j = 0; j < 4; j++) acc[mt][nt][j] = 0.0f;
    gemm_mainloop_f16(A16, Wm1, nrows, dsm, row0, tid, wid, g, tg, acc);

    // stage relu(acc + bm1) into smem [128][65] (tile memory dead after mainloop)
    float* st  = (float*)dsm;                 // 33280 B
    float* sW  = st + 128 * 65;               // 4096 B
    float* sbv = sW + 64 * 16;                // 64 B  (total 37440 <= SMEM_HEAD)
#pragma unroll
    for (int mt = 0; mt < 2; mt++) {
        int rl0 = wid * 32 + mt * 16 + g;
#pragma unroll
        for (int nt = 0; nt < 8; nt++) {
            int c = nt * 8 + tg * 2;
            float b0 = __ldg(&bm1[c]), b1 = __ldg(&bm1[c + 1]);
            st[rl0 * 65 + c]           = fmaxf(acc[mt][nt][0] + b0, 0.0f);
            st[rl0 * 65 + c + 1]       = fmaxf(acc[mt][nt][1] + b1, 0.0f);
            st[(rl0 + 8) * 65 + c]     = fmaxf(acc[mt][nt][2] + b0, 0.0f);
            st[(rl0 + 8) * 65 + c + 1] = fmaxf(acc[mt][nt][3] + b1, 0.0f);
        }
    }
    for (int i = tid; i < HH * CC; i += 128) sW[i] = Wm2[i];
    if (tid < CC) sbv[tid] = bm2[tid];
    __syncthreads();

    int r = row0 + tid;                       // one row per thread
    if (r < nrows) {
        float lg[CC];
#pragma unroll
        for (int c = 0; c < CC; c++) lg[c] = sbv[c];
        const float* mrow = st + tid * 65;    // stride 65 -> conflict-free
#pragma unroll
        for (int k = 0; k < HH; k++) {
            float av = mrow[k];
#pragma unroll
            for (int c = 0; c < CC; c++) lg[c] += av * sW[k * CC + c];
        }
        float mx = lg[0];
#pragma unroll
        for (int c = 1; c < CC; c++) mx = fmaxf(mx, lg[c]);
        float ssum = 0.0f;
#pragma unroll
        for (int c = 0; c < CC; c++) { lg[c] = __expf(lg[c] - mx); ssum += lg[c]; }
        float inv = 1.0f / ssum;
        float4* op = (float4*)(out + (size_t)r * CC);
#pragma unroll
        for (int c4 = 0; c4 < 4; c4++)
            op[c4] = make_float4(lg[c4 * 4] * inv, lg[c4 * 4 + 1] * inv,
                                 lg[c4 * 4 + 2] * inv, lg[c4 * 4 + 3] * inv);
    }
}

// ---- edge aggregation: HALF-WARP per node, 4x unrolled, fp16 in/out ----
// out[i] = relu( dinv[i] * ( dinv[i]*h[i] + sum_e val'[e]*h[col[e]] ) + bias )
__global__ void k_agg16(const uint2* __restrict__ hp, const float* __restrict__ bias,
                        uint2* __restrict__ out) {
    int gt = blockIdx.x * blockDim.x + threadIdx.x;
    int w  = gt >> 4;                          // node = half-warp
    int l  = gt & 15;                          // lane: feats 4l..4l+3
    if (w >= NN) return;
    float di = g_dinv[w];

    uint2 hv = hp[(size_t)w * 16 + l];
    float2 h0 = __half22float2(*(const __half2*)&hv.x);
    float2 h1 = __half22float2(*(const __half2*)&hv.y);
    float a0 = di * h0.x, a1 = di * h0.y, a2 = di * h1.x, a3 = di * h1.y;

    int e  = __ldg(&g_rowptr[w]);
    int e1 = __ldg(&g_rowptr[w + 1]);
    for (; e + 4 <= e1; e += 4) {
        uint2 ev0 = g_edge[e],     ev1 = g_edge[e + 1];
        uint2 ev2 = g_edge[e + 2], ev3 = g_edge[e + 3];
        uint2 p0 = hp[(size_t)ev0.x * 16 + l];
        uint2 p1 = hp[(size_t)ev1.x * 16 + l];
        uint2 p2 = hp[(size_t)ev2.x * 16 + l];
        uint2 p3 = hp[(size_t)ev3.x * 16 + l];
        float v0 = __uint_as_float(ev0.y), v1 = __uint_as_float(ev1.y);
        float v2 = __uint_as_float(ev2.y), v3 = __uint_as_float(ev3.y);
        float2 q;
        q = __half22float2(*(const __half2*)&p0.x); a0 += v0 * q.x; a1 += v0 * q.y;
        q = __half22float2(*(const __half2*)&p0.y); a2 += v0 * q.x; a3 += v0 * q.y;
        q = __half22float2(*(const __half2*)&p1.x); a0 += v1 * q.x; a1 += v1 * q.y;
        q = __half22float2(*(const __half2*)&p1.y); a2 += v1 * q.x; a3 += v1 * q.y;
        q = __half22float2(*(const __half2*)&p2.x); a0 += v2 * q.x; a1 += v2 * q.y;
        q = __half22float2(*(const __half2*)&p2.y); a2 += v2 * q.x; a3 += v2 * q.y;
        q = __half22float2(*(const __half2*)&p3.x); a0 += v3 * q.x; a1 += v3 * q.y;
        q = __half22float2(*(const __half2*)&p3.y); a2 += v3 * q.x; a3 += v3 * q.y;
    }
    for (; e < e1; e++) {
        uint2 ev = g_edge[e];
        uint2 p  = hp[(size_t)ev.x * 16 + l];
        float v  = __uint_as_float(ev.y);
        float2 q;
        q = __half22float2(*(const __half2*)&p.x); a0 += v * q.x; a1 += v * q.y;
        q = __half22float2(*(const __half2*)&p.y); a2 += v * q.x; a3 += v * q.y;
    }
    float4 bv = *(const float4*)&bias[4 * l];
    __half2 o0 = __floats2half2_rn(fmaxf(di * a0 + bv.x, 0.0f),
                                   fmaxf(di * a1 + bv.y, 0.0f));
    __half2 o1 = __floats2half2_rn(fmaxf(di * a2 + bv.z, 0.0f),
                                   fmaxf(di * a3 + bv.w, 0.0f));
    out[(size_t)w * 16 + l] = make_uint2(*(uint32_t*)&o0, *(uint32_t*)&o1);
}

// ---------------- launch ----------------
extern "C" void kernel_launch(void* const* d_in, const int* in_sizes, int n_in,
                              void* d_out, int out_size) {
    const float* x   = (const float*)d_in[0];
    const void*  ei  = d_in[1];
    const float* ew  = (const float*)d_in[2];
    const float* W1  = (const float*)d_in[3];
    const float* b1  = (const float*)d_in[4];
    const float* W2  = (const float*)d_in[5];
    const float* b2  = (const float*)d_in[6];
    const float* Wm1 = (const float*)d_in[7];
    const float* bm1 = (const float*)d_in[8];
    const float* Wm2 = (const float*)d_in[9];
    const float* bm2 = (const float*)d_in[10];
    float* out = (float*)d_out;

    float *pA, *pB;
    cudaGetSymbolAddress((void**)&pA, g_bufA);
    cudaGetSymbolAddress((void**)&pB, g_bufB);
    __half2* pA16 = (__half2*)pA;
    __half2* pB16 = (__half2*)pB;

    static cudaStream_t s2 = 0;
    static cudaEvent_t evA = 0, evB = 0;
    if (!s2) {
        cudaStreamCreateWithFlags(&s2, cudaStreamNonBlocking);
        cudaEventCreateWithFlags(&evA, cudaEventDisableTiming);
        cudaEventCreateWithFlags(&evB, cudaEventDisableTiming);
        cudaFuncSetAttribute(gemm_tc<INF>, cudaFuncAttributeMaxDynamicSharedMemorySize, SMEM_DYN);
        cudaFuncSetAttribute(gemm_f16,     cudaFuncAttributeMaxDynamicSharedMemorySize, SMEM_F16);
        cudaFuncSetAttribute(gemm_head,    cudaFuncAttributeMaxDynamicSharedMemorySize, SMEM_HEAD);
    }

    const int gemm_grid = (NN + 127) / 128;
    const int agg_grid  = (NN * 16 + 255) / 256;
    const int nblk      = (NN + 1023) / 1024;        // 98

    // fork: GEMM1 (x @ W1 -> fp16 h) alongside CSR build
    cudaEventRecord(evA, 0);
    cudaStreamWaitEvent(s2, evA, 0);
    gemm_tc<INF><<<gemm_grid, 128, SMEM_DYN, s2>>>(x, W1, pA16, NN);
    cudaEventRecord(evB, s2);

    // CSR build on main stream (single packed atomic per edge in pass 1)
    k_init<<<(NN + 255) / 256, 256>>>((const unsigned int*)ei);
    k_degcnt<<<(EE + 255) / 256, 256>>>(ei, ew);
    k_scanA<<<nblk, 1024>>>();
    k_scanC<<<(NN + 255) / 256, 256>>>();
    k_scatter<<<(EE + 255) / 256, 256>>>(ei, ew);

    cudaStreamWaitEvent(0, evB, 0);                  // join GEMM1

    k_agg16<<<agg_grid, 256>>>((const uint2*)pA16, b1, (uint2*)pB16);   // conv1+relu
    gemm_f16<<<gemm_grid, 128, SMEM_F16>>>((const uint2*)pB16, W2, pA16, NN);
    k_agg16<<<agg_grid, 256>>>((const uint2*)pA16, b2, (uint2*)pB16);   // conv2+relu
    gemm_head<<<gemm_grid, 128, SMEM_HEAD>>>((const uint2*)pB16, Wm1, bm1, Wm2, bm2, out, NN);
}

// round 13
// speedup vs baseline: 1.2114x; 1.0013x over previous
#include <cuda_runtime.h>
#include <cuda_bf16.h>
#include <cuda_fp16.h>
#include <cstdint>

#define NN  100000
#define EE  1600000
#define INF 256
#define HH  64
#define CC  16

#define FIXSCALE 33554432.0f                 // 2^25
#define CNTSHIFT 40

// ---------------- scratch (no allocations allowed -> device globals) ----------------
__device__ float g_bufA[(size_t)NN * HH];   // holds fp16 h (12.8 MB)
__device__ float g_bufB[(size_t)NN * HH];   // holds fp16 h (12.8 MB)
__device__ unsigned long long g_degcnt[NN]; // packed: cnt<<40 | deg_fixed(2^-25)
__device__ float g_dinv[NN];
__device__ int   g_rowptr[NN + 1];
__device__ int   g_rank[EE];                // rank of edge within its dst bucket
__device__ uint2 g_edge[EE];                // packed (src, val) 8B
__device__ int   g_idx64;
__device__ int   g_blksum[128];
__device__ int   g_blkoff[128];
__device__ int   g_arrive;

// edge_index may be int64 (reference declares it) or int32 (jax x64-disabled
// canonicalization). Detected at runtime; branch on device flag.
__device__ __forceinline__ int ld_idx(const void* ei, long long pos) {
    if (g_idx64)
        return (int)((const long long*)ei)[pos];
    return ((const int*)ei)[pos];
}

// init: zero degcnt/arrive; thread 0 detects index width (odd 32-bit words of
// first 64 entries all zero iff int64, since indices < 1e5).
__global__ void k_init(const unsigned int* ei) {
    int i = blockIdx.x * blockDim.x + threadIdx.x;
    if (i < NN) g_degcnt[i] = 0ull;
    if (i == 0) {
        unsigned v = 0;
        for (int j = 0; j < 64; j++) v |= ei[2 * j + 1];
        g_idx64 = (v == 0) ? 1 : 0;
        g_arrive = 0;
    }
}

// pass 1 over edges: ONE packed 64-bit atomic per edge.
// add = (1 << 40) | round(ew * 2^25); return's high bits = rank in dst bucket.
__global__ void k_degcnt(const void* ei, const float* __restrict__ ew) {
    int e = blockIdx.x * blockDim.x + threadIdx.x;
    if (e < EE) {
        int d = ld_idx(ei, (long long)EE + e);       // dst row
        unsigned long long add =
            (1ull << CNTSHIFT) |
            (unsigned long long)(unsigned)__float2uint_rn(ew[e] * FIXSCALE);
        unsigned long long old = atomicAdd(&g_degcnt[d], add);
        g_rank[e] = (int)(old >> CNTSHIFT);
    }
}

// ---- scan phase A: shuffle block scan; ticketed last block scans block sums ----
__global__ void k_scanA() {
    __shared__ int wsum[32];
    __shared__ int sb[128];
    __shared__ int s_last;
    const int t    = threadIdx.x;
    const int lane = t & 31;
    const int warp = t >> 5;
    int i = blockIdx.x * 1024 + t;
    int v = (i < NN) ? (int)(g_degcnt[i] >> CNTSHIFT) : 0;

    int x = v;
#pragma unroll
    for (int off = 1; off < 32; off <<= 1) {
        int y = __shfl_up_sync(0xffffffff, x, off);
        if (lane >= off) x += y;
    }
    if (lane == 31) wsum[warp] = x;
    __syncthreads();
    if (warp == 0) {
        int w = (lane < 32) ? wsum[lane] : 0;
#pragma unroll
        for (int off = 1; off < 32; off <<= 1) {
            int y = __shfl_up_sync(0xffffffff, w, off);
            if (lane >= off) w += y;
        }
        wsum[lane] = w;                              // inclusive warp sums
    }
    __syncthreads();
    int incl = x + (warp ? wsum[warp - 1] : 0);
    if (i < NN) g_rowptr[i] = incl - v;              // block-local exclusive
    if (t == 1023) g_blksum[blockIdx.x] = incl;
    __threadfence();
    __syncthreads();
    if (t == 0) s_last = (atomicAdd(&g_arrive, 1) == (int)gridDim.x - 1);
    __syncthreads();
    if (s_last) {                                    // uniform branch
        int nb = (int)gridDim.x;
        int bv = (t < 128 && t < nb) ? g_blksum[t] : 0;
        if (t < 128) sb[t] = bv;
        __syncthreads();
        for (int off = 1; off < 128; off <<= 1) {
            int a = (t < 128 && t >= off) ? sb[t - off] : 0;
            __syncthreads();
            if (t < 128) sb[t] += a;
            __syncthreads();
        }
        if (t < nb) g_blkoff[t] = sb[t] - bv;        // exclusive
    }
}

__global__ void k_scanC() {
    int i = blockIdx.x * blockDim.x + threadIdx.x;
    if (i < NN) {
        g_rowptr[i] = g_rowptr[i] + g_blkoff[i >> 10];
        unsigned long long dc = g_degcnt[i];
        float deg = (float)((double)(dc & ((1ull << CNTSHIFT) - 1)) *
                            (1.0 / (double)FIXSCALE));
        g_dinv[i] = rsqrtf(1.0f + deg);              // +1 = self-loop weight
    }
    if (i == 0) g_rowptr[NN] = EE;
}

// pass 2 over edges: atomic-free placement via rowptr + rank, packed 8B store.
// stored val = dinv[src]*w  (dinv[dst] applied once per node in agg)
__global__ void k_scatter(const void* ei, const float* __restrict__ ew) {
    int e = blockIdx.x * blockDim.x + threadIdx.x;
    if (e < EE) {
        int s = ld_idx(ei, e);
        int d = ld_idx(ei, (long long)EE + e);
        int pos = g_rowptr[d] + g_rank[e];
        float v = g_dinv[s] * ew[e];
        g_edge[pos] = make_uint2((unsigned)s, __float_as_uint(v));
    }
}

// ================================ GEMM kernels ================================
#define APAD 72                               // 16-bit row stride (conflict-free frags)

// ---- GEMM1: fp32 A, bf16 hi/lo split (3 MMAs), fp16 out ----
#define SM_AHI 0
#define SM_ALO (128 * APAD)
#define SM_BHI (2 * 128 * APAD)
#define SM_BLO (2 * 128 * APAD + 64 * APAD)
#define SMEM_DYN ((2 * 128 * APAD + 2 * 64 * APAD) * 2)   // 55296 B

// ---- GEMM2/head: fp16 A exact (2 MMAs), W hi/lo split ----
#define SMF_A   0
#define SMF_BHI (128 * APAD)
#define SMF_BLO (128 * APAD + 64 * APAD)
#define SMEM_F16 ((128 * APAD + 2 * 64 * APAD) * 2)        // 36864 B
#define SMEM_HEAD 37504                                    // head stage needs 37440

__device__ __forceinline__ void mma_bf16(float* c, const uint32_t* a,
                                         uint32_t b0, uint32_t b1) {
    asm volatile(
        "mma.sync.aligned.m16n8k16.row.col.f32.bf16.bf16.f32 "
        "{%0,%1,%2,%3}, {%4,%5,%6,%7}, {%8,%9}, {%0,%1,%2,%3};"
        : "+f"(c[0]), "+f"(c[1]), "+f"(c[2]), "+f"(c[3])
        : "r"(a[0]), "r"(a[1]), "r"(a[2]), "r"(a[3]), "r"(b0), "r"(b1));
}
__device__ __forceinline__ void mma_f16(float* c, const uint32_t* a,
                                        uint32_t b0, uint32_t b1) {
    asm volatile(
        "mma.sync.aligned.m16n8k16.row.col.f32.f16.f16.f32 "
        "{%0,%1,%2,%3}, {%4,%5,%6,%7}, {%8,%9}, {%0,%1,%2,%3};"
        : "+f"(c[0]), "+f"(c[1]), "+f"(c[2]), "+f"(c[3])
        : "r"(a[0]), "r"(a[1]), "r"(a[2]), "r"(a[3]), "r"(b0), "r"(b1));
}

// bf16-split mainloop (GEMM1), fp32 A
template <int KTOT>
__device__ __forceinline__ void gemm_mainloop_bf16(
    const float* __restrict__ A, const float* __restrict__ W, int nrows,
    char* dsm, int row0, int tid, int wid, int g, int tg, float acc[2][8][4]) {
    __nv_bfloat16* Ahi = (__nv_bfloat16*)dsm + SM_AHI;
    __nv_bfloat16* Alo = (__nv_bfloat16*)dsm + SM_ALO;
    __nv_bfloat16* Bhi = (__nv_bfloat16*)dsm + SM_BHI;
    __nv_bfloat16* Blo = (__nv_bfloat16*)dsm + SM_BLO;
    const int m0 = wid * 32;

    for (int kt = 0; kt < KTOT; kt += 64) {
#pragma unroll
        for (int it = 0; it < 8; it++) {
            int chunk = it * 128 + tid;
            int r  = chunk >> 3;
            int kc = (chunk & 7) * 8;
            int row = row0 + r;
            float v[8];
            if (row < nrows) {
                const float4* p = (const float4*)(A + (size_t)row * KTOT + kt + kc);
                float4 a = p[0], b = p[1];
                v[0] = a.x; v[1] = a.y; v[2] = a.z; v[3] = a.w;
                v[4] = b.x; v[5] = b.y; v[6] = b.z; v[7] = b.w;
            } else {
#pragma unroll
                for (int j = 0; j < 8; j++) v[j] = 0.0f;
            }
#pragma unroll
            for (int j = 0; j < 4; j++) {
                __nv_bfloat162 h, l;
                h.x = __float2bfloat16(v[2 * j]);
                h.y = __float2bfloat16(v[2 * j + 1]);
                l.x = __float2bfloat16(v[2 * j]     - __bfloat162float(h.x));
                l.y = __float2bfloat16(v[2 * j + 1] - __bfloat162float(h.y));
                *(__nv_bfloat162*)&Ahi[r * APAD + kc + 2 * j] = h;
                *(__nv_bfloat162*)&Alo[r * APAD + kc + 2 * j] = l;
            }
        }
#pragma unroll
        for (int it = 0; it < 32; it++) {
            int idx = it * 128 + tid;
            int n = idx & 63, k = idx >> 6;
            float w = W[(size_t)(kt + k) * HH + n];
            __nv_bfloat16 h = __float2bfloat16(w);
            Bhi[n * APAD + k] = h;
            Blo[n * APAD + k] = __float2bfloat16(w - __bfloat162float(h));
        }
        __syncthreads();

#pragma unroll
        for (int kc = 0; kc < 64; kc += 16) {
            uint32_t ah[2][4], al[2][4];
#pragma unroll
            for (int mt = 0; mt < 2; mt++) {
                int r = m0 + mt * 16 + g;
                ah[mt][0] = *(const uint32_t*)&Ahi[r * APAD + kc + tg * 2];
                ah[mt][1] = *(const uint32_t*)&Ahi[(r + 8) * APAD + kc + tg * 2];
                ah[mt][2] = *(const uint32_t*)&Ahi[r * APAD + kc + 8 + tg * 2];
                ah[mt][3] = *(const uint32_t*)&Ahi[(r + 8) * APAD + kc + 8 + tg * 2];
                al[mt][0] = *(const uint32_t*)&Alo[r * APAD + kc + tg * 2];
                al[mt][1] = *(const uint32_t*)&Alo[(r + 8) * APAD + kc + tg * 2];
                al[mt][2] = *(const uint32_t*)&Alo[r * APAD + kc + 8 + tg * 2];
                al[mt][3] = *(const uint32_t*)&Alo[(r + 8) * APAD + kc + 8 + tg * 2];
            }
#pragma unroll
            for (int nt = 0; nt < 8; nt++) {
                int n = nt * 8 + g;
                uint32_t bh0 = *(const uint32_t*)&Bhi[n * APAD + kc + tg * 2];
                uint32_t bh1 = *(const uint32_t*)&Bhi[n * APAD + kc + 8 + tg * 2];
                uint32_t bl0 = *(const uint32_t*)&Blo[n * APAD + kc + tg * 2];
                uint32_t bl1 = *(const uint32_t*)&Blo[n * APAD + kc + 8 + tg * 2];
#pragma unroll
                for (int mt = 0; mt < 2; mt++) {
                    mma_bf16(acc[mt][nt], ah[mt], bh0, bh1);   // hi*hi
                    mma_bf16(acc[mt][nt], ah[mt], bl0, bl1);   // hi*lo
                    mma_bf16(acc[mt][nt], al[mt], bh0, bh1);   // lo*hi
                }
            }
        }
        __syncthreads();
    }
}

// fp16-exact-A mainloop (K=64): A from fp16 table, W split hi/lo (2 MMAs)
__device__ __forceinline__ void gemm_mainloop_f16(
    const uint2* __restrict__ A16, const float* __restrict__ W, int nrows,
    char* dsm, int row0, int tid, int wid, int g, int tg, float acc[2][8][4]) {
    __half* Ah  = (__half*)dsm + SMF_A;
    __half* Bhi = (__half*)dsm + SMF_BHI;
    __half* Blo = (__half*)dsm + SMF_BLO;
    const int m0 = wid * 32;

#pragma unroll
    for (int it = 0; it < 16; it++) {                // A: 128 rows x 64 fp16
        int idx = it * 128 + tid;
        int r = idx >> 4, c = idx & 15;              // c = 8B chunk (4 halfs)
        int row = row0 + r;
        uint2 v = (row < nrows) ? A16[(size_t)row * 16 + c] : make_uint2(0u, 0u);
        *(uint2*)&Ah[r * APAD + c * 4] = v;
    }
#pragma unroll
    for (int it = 0; it < 32; it++) {                // B: W[k][n] -> Bs[n][k]
        int idx = it * 128 + tid;
        int n = idx & 63, k = idx >> 6;
        float w = W[(size_t)k * HH + n];
        __half h = __float2half_rn(w);
        Bhi[n * APAD + k] = h;
        Blo[n * APAD + k] = __float2half_rn(w - __half2float(h));
    }
    __syncthreads();

#pragma unroll
    for (int kc = 0; kc < 64; kc += 16) {
        uint32_t a[2][4];
#pragma unroll
        for (int mt = 0; mt < 2; mt++) {
            int r = m0 + mt * 16 + g;
            a[mt][0] = *(const uint32_t*)&Ah[r * APAD + kc + tg * 2];
            a[mt][1] = *(const uint32_t*)&Ah[(r + 8) * APAD + kc + tg * 2];
            a[mt][2] = *(const uint32_t*)&Ah[r * APAD + kc + 8 + tg * 2];
            a[mt][3] = *(const uint32_t*)&Ah[(r + 8) * APAD + kc + 8 + tg * 2];
        }
#pragma unroll
        for (int nt = 0; nt < 8; nt++) {
            int n = nt * 8 + g;
            uint32_t bh0 = *(const uint32_t*)&Bhi[n * APAD + kc + tg * 2];
            uint32_t bh1 = *(const uint32_t*)&Bhi[n * APAD + kc + 8 + tg * 2];
            uint32_t bl0 = *(const uint32_t*)&Blo[n * APAD + kc + tg * 2];
            uint32_t bl1 = *(const uint32_t*)&Blo[n * APAD + kc + 8 + tg * 2];
#pragma unroll
            for (int mt = 0; mt < 2; mt++) {
                mma_f16(acc[mt][nt], a[mt], bh0, bh1);   // A*Whi
                mma_f16(acc[mt][nt], a[mt], bl0, bl1);   // A*Wlo
            }
        }
    }
    __syncthreads();                                 // smem reusable after this
}

// fp16 epilogue writer (h layout: row * 32 half2, feature-linear)
__device__ __forceinline__ void write_h16(__half2* out, int nrows, int row0,
                                          int wid, int g, int tg, float acc[2][8][4]) {
#pragma unroll
    for (int mt = 0; mt < 2; mt++) {
        int r0 = row0 + wid * 32 + mt * 16 + g;
        int r1 = r0 + 8;
#pragma unroll
        for (int nt = 0; nt < 8; nt++) {
            int h2c = nt * 4 + tg;
            if (r0 < nrows)
                out[(size_t)r0 * 32 + h2c] = __floats2half2_rn(acc[mt][nt][0], acc[mt][nt][1]);
            if (r1 < nrows)
                out[(size_t)r1 * 32 + h2c] = __floats2half2_rn(acc[mt][nt][2], acc[mt][nt][3]);
        }
    }
}

// GEMM1: x(fp32) @ W1 -> fp16 h
template <int KTOT>
__global__ void __launch_bounds__(128)
gemm_tc(const float* __restrict__ A, const float* __restrict__ W,
        __half2* __restrict__ out, int nrows) {
    extern __shared__ char dsm[];
    const int tid = threadIdx.x, wid = tid >> 5, lane = tid & 31;
    const int g = lane >> 2, tg = lane & 3;
    const int row0 = blockIdx.x * 128;
    float acc[2][8][4];
#pragma unroll
    for (int mt = 0; mt < 2; mt++)
#pragma unroll
        for (int nt = 0; nt < 8; nt++)
#pragma unroll
            for (int j = 0; j < 4; j++) acc[mt][nt][j] = 0.0f;
    gemm_mainloop_bf16<KTOT>(A, W, nrows, dsm, row0, tid, wid, g, tg, acc);
    write_h16(out, nrows, row0, wid, g, tg, acc);
}

// GEMM2: h(fp16) @ W2 -> fp16 h
__global__ void __launch_bounds__(128)
gemm_f16(const uint2* __restrict__ A16, const float* __restrict__ W,
         __half2* __restrict__ out, int nrows) {
    extern __shared__ char dsm[];
    const int tid = threadIdx.x, wid = tid >> 5, lane = tid & 31;
    const int g = lane >> 2, tg = lane & 3;
    const int row0 = blockIdx.x * 128;
    float acc[2][8][4];
#pragma unroll
    for (int mt = 0; mt < 2; mt++)
#pragma unroll
        for (int nt = 0; nt < 8; nt++)
#pragma unroll
            for (int j = 0; j < 4; j++) acc[mt][nt][j] = 0.0f;
    gemm_mainloop_f16(A16, W, nrows, dsm, row0, tid, wid, g, tg, acc);
    write_h16(out, nrows, row0, wid, g, tg, acc);
}

// GEMM3 (fp16 A) + bias/relu + fused MLP head (logits @ Wm2 + bm2, softmax)
__global__ void __launch_bounds__(128)
gemm_head(const uint2* __restrict__ A16, const float* __restrict__ Wm1,
          const float* __restrict__ bm1, const float* __restrict__ Wm2,
          const float* __restrict__ bm2, float* __restrict__ out, int nrows) {
    extern __shared__ char dsm[];
    const int tid = threadIdx.x, wid = tid >> 5, lane = tid & 31;
    const int g = lane >> 2, tg = lane & 3;
    const int row0 = blockIdx.x * 128;
    float acc[2][8][4];
#pragma unroll
    for (int mt = 0; mt < 2; mt++)
#pragma unroll
        for (int nt = 0; nt < 8; nt++)
#pragma unroll
            for (int j = 0; j < 4; j++) acc[mt][nt][j] = 0.0f;
    gemm_mainloop_f16(A16, Wm1, nrows, dsm, row0, tid, wid, g, tg, acc);

    // stage relu(acc + bm1) into smem [128][65] (tile memory dead after mainloop)
    float* st  = (float*)dsm;                 // 33280 B
    float* sW  = st + 128 * 65;               // 4096 B
    float* sbv = sW + 64 * 16;                // 64 B  (total 37440 <= SMEM_HEAD)
#pragma unroll
    for (int mt = 0; mt < 2; mt++) {
        int rl0 = wid * 32 + mt * 16 + g;
#pragma unroll
        for (int nt = 0; nt < 8; nt++) {
            int c = nt * 8 + tg * 2;
            float b0 = __ldg(&bm1[c]), b1 = __ldg(&bm1[c + 1]);
            st[rl0 * 65 + c]           = fmaxf(acc[mt][nt][0] + b0, 0.0f);
            st[rl0 * 65 + c + 1]       = fmaxf(acc[mt][nt][1] + b1, 0.0f);
            st[(rl0 + 8) * 65 + c]     = fmaxf(acc[mt][nt][2] + b0, 0.0f);
            st[(rl0 + 8) * 65 + c + 1] = fmaxf(acc[mt][nt][3] + b1, 0.0f);
        }
    }
    for (int i = tid; i < HH * CC; i += 128) sW[i] = Wm2[i];
    if (tid < CC) sbv[tid] = bm2[tid];
    __syncthreads();

    int r = row0 + tid;                       // one row per thread
    if (r < nrows) {
        float lg[CC];
#pragma unroll
        for (int c = 0; c < CC; c++) lg[c] = sbv[c];
        const float* mrow = st + tid * 65;    // stride 65 -> conflict-free
#pragma unroll
        for (int k = 0; k < HH; k++) {
            float av = mrow[k];
#pragma unroll
            for (int c = 0; c < CC; c++) lg[c] += av * sW[k * CC + c];
        }
        float mx = lg[0];
#pragma unroll
        for (int c = 1; c < CC; c++) mx = fmaxf(mx, lg[c]);
        float ssum = 0.0f;
#pragma unroll
        for (int c = 0; c < CC; c++) { lg[c] = __expf(lg[c] - mx); ssum += lg[c]; }
        float inv = 1.0f / ssum;
        float4* op = (float4*)(out + (size_t)r * CC);
#pragma unroll
        for (int c4 = 0; c4 < 4; c4++)
            op[c4] = make_float4(lg[c4 * 4] * inv, lg[c4 * 4 + 1] * inv,
                                 lg[c4 * 4 + 2] * inv, lg[c4 * 4 + 3] * inv);
    }
}

// ---- edge aggregation: QUARTER-WARP per node (8 lanes x 16B = 128B/row) ----
// out[i] = relu( dinv[i] * ( dinv[i]*h[i] + sum_e val'[e]*h[col[e]] ) + bias )
__device__ __forceinline__ void acc8(uint4 p, float v, float* a) {
    float2 q;
    q = __half22float2(*(const __half2*)&p.x); a[0] += v * q.x; a[1] += v * q.y;
    q = __half22float2(*(const __half2*)&p.y); a[2] += v * q.x; a[3] += v * q.y;
    q = __half22float2(*(const __half2*)&p.z); a[4] += v * q.x; a[5] += v * q.y;
    q = __half22float2(*(const __half2*)&p.w); a[6] += v * q.x; a[7] += v * q.y;
}

__global__ void k_agg8(const uint4* __restrict__ hp, const float* __restrict__ bias,
                       uint4* __restrict__ out) {
    int gt = blockIdx.x * blockDim.x + threadIdx.x;
    int w  = gt >> 3;                          // node = quarter-warp
    int l  = gt & 7;                           // lane: feats 8l..8l+7
    if (w >= NN) return;
    float di = g_dinv[w];

    float a[8];
    {
        uint4 hv = hp[(size_t)w * 8 + l];
        float2 q;
        q = __half22float2(*(const __half2*)&hv.x); a[0] = di * q.x; a[1] = di * q.y;
        q = __half22float2(*(const __half2*)&hv.y); a[2] = di * q.x; a[3] = di * q.y;
        q = __half22float2(*(const __half2*)&hv.z); a[4] = di * q.x; a[5] = di * q.y;
        q = __half22float2(*(const __half2*)&hv.w); a[6] = di * q.x; a[7] = di * q.y;
    }

    int e  = __ldg(&g_rowptr[w]);
    int e1 = __ldg(&g_rowptr[w + 1]);
    for (; e + 4 <= e1; e += 4) {
        uint2 ev0 = g_edge[e],     ev1 = g_edge[e + 1];
        uint2 ev2 = g_edge[e + 2], ev3 = g_edge[e + 3];
        uint4 p0 = hp[(size_t)ev0.x * 8 + l];
        uint4 p1 = hp[(size_t)ev1.x * 8 + l];
        uint4 p2 = hp[(size_t)ev2.x * 8 + l];
        uint4 p3 = hp[(size_t)ev3.x * 8 + l];
        acc8(p0, __uint_as_float(ev0.y), a);
        acc8(p1, __uint_as_float(ev1.y), a);
        acc8(p2, __uint_as_float(ev2.y), a);
        acc8(p3, __uint_as_float(ev3.y), a);
    }
    for (; e < e1; e++) {
        uint2 ev = g_edge[e];
        uint4 p  = hp[(size_t)ev.x * 8 + l];
        acc8(p, __uint_as_float(ev.y), a);
    }

    float4 b0 = *(const float4*)&bias[8 * l];
    float4 b1 = *(const float4*)&bias[8 * l + 4];
    __half2 o0 = __floats2half2_rn(fmaxf(di * a[0] + b0.x, 0.0f),
                                   fmaxf(di * a[1] + b0.y, 0.0f));
    __half2 o1 = __floats2half2_rn(fmaxf(di * a[2] + b0.z, 0.0f),
                                   fmaxf(di * a[3] + b0.w, 0.0f));
    __half2 o2 = __floats2half2_rn(fmaxf(di * a[4] + b1.x, 0.0f),
                                   fmaxf(di * a[5] + b1.y, 0.0f));
    __half2 o3 = __floats2half2_rn(fmaxf(di * a[6] + b1.z, 0.0f),
                                   fmaxf(di * a[7] + b1.w, 0.0f));
    uint4 o;
    o.x = *(uint32_t*)&o0; o.y = *(uint32_t*)&o1;
    o.z = *(uint32_t*)&o2; o.w = *(uint32_t*)&o3;
    out[(size_t)w * 8 + l] = o;
}

// ---------------- launch ----------------
extern "C" void kernel_launch(void* const* d_in, const int* in_sizes, int n_in,
                              void* d_out, int out_size) {
    const float* x   = (const float*)d_in[0];
    const void*  ei  = d_in[1];
    const float* ew  = (const float*)d_in[2];
    const float* W1  = (const float*)d_in[3];
    const float* b1  = (const float*)d_in[4];
    const float* W2  = (const float*)d_in[5];
    const float* b2  = (const float*)d_in[6];
    const float* Wm1 = (const float*)d_in[7];
    const float* bm1 = (const float*)d_in[8];
    const float* Wm2 = (const float*)d_in[9];
    const float* bm2 = (const float*)d_in[10];
    float* out = (float*)d_out;

    float *pA, *pB;
    cudaGetSymbolAddress((void**)&pA, g_bufA);
    cudaGetSymbolAddress((void**)&pB, g_bufB);
    __half2* pA16 = (__half2*)pA;
    __half2* pB16 = (__half2*)pB;

    static cudaStream_t s2 = 0;
    static cudaEvent_t evA = 0, evB = 0;
    if (!s2) {
        cudaStreamCreateWithFlags(&s2, cudaStreamNonBlocking);
        cudaEventCreateWithFlags(&evA, cudaEventDisableTiming);
        cudaEventCreateWithFlags(&evB, cudaEventDisableTiming);
        cudaFuncSetAttribute(gemm_tc<INF>, cudaFuncAttributeMaxDynamicSharedMemorySize, SMEM_DYN);
        cudaFuncSetAttribute(gemm_f16,     cudaFuncAttributeMaxDynamicSharedMemorySize, SMEM_F16);
        cudaFuncSetAttribute(gemm_head,    cudaFuncAttributeMaxDynamicSharedMemorySize, SMEM_HEAD);
    }

    const int gemm_grid = (NN + 127) / 128;
    const int agg_grid  = (NN * 8 + 255) / 256;      // 3125
    const int nblk      = (NN + 1023) / 1024;        // 98

    // fork: GEMM1 (x @ W1 -> fp16 h) alongside CSR build
    cudaEventRecord(evA, 0);
    cudaStreamWaitEvent(s2, evA, 0);
    gemm_tc<INF><<<gemm_grid, 128, SMEM_DYN, s2>>>(x, W1, pA16, NN);
    cudaEventRecord(evB, s2);

    // CSR build on main stream (single packed atomic per edge in pass 1)
    k_init<<<(NN + 255) / 256, 256>>>((const unsigned int*)ei);
    k_degcnt<<<(EE + 255) / 256, 256>>>(ei, ew);
    k_scanA<<<nblk, 1024>>>();
    k_scanC<<<(NN + 255) / 256, 256>>>();
    k_scatter<<<(EE + 255) / 256, 256>>>(ei, ew);

    cudaStreamWaitEvent(0, evB, 0);                  // join GEMM1

    k_agg8<<<agg_grid, 256>>>((const uint4*)pA16, b1, (uint4*)pB16);    // conv1+relu
    gemm_f16<<<gemm_grid, 128, SMEM_F16>>>((const uint2*)pB16, W2, pA16, NN);
    k_agg8<<<agg_grid, 256>>>((const uint4*)pA16, b2, (uint4*)pB16);    // conv2+relu
    gemm_head<<<gemm_grid, 128, SMEM_HEAD>>>((const uint2*)pB16, Wm1, bm1, Wm2, bm2, out, NN);
}

// round 15
// speedup vs baseline: 1.2440x; 1.0269x over previous
#include <cuda_runtime.h>
#include <cuda_bf16.h>
#include <cuda_fp16.h>
#include <cstdint>

#define NN  100000
#define EE  1600000
#define INF 256
#define HH  64
#define CC  16

#define FIXSCALE 33554432.0f                 // 2^25
#define CNTSHIFT 40

#define ROWSPLIT 50048                       // 391 gemm blocks, 1564 agg blocks

// ---------------- scratch (no allocations allowed -> device globals) ----------------
// fp16 h needs 12.8 MB; bufA (25.6 MB) holds TWO fp16 buffers (hA lo-half, hC hi-half).
__device__ float g_bufA[(size_t)NN * HH];   // hA = [0,12.8MB), hC = [12.8,25.6MB)
__device__ float g_bufB[(size_t)NN * HH];   // hB (agg outputs)
__device__ unsigned long long g_degcnt[NN]; // packed: cnt<<40 | deg_fixed(2^-25)
__device__ float g_dinv[NN];
__device__ int   g_rowptr[NN + 1];
__device__ int   g_rank[EE];                // rank of edge within its dst bucket
__device__ uint2 g_edge[EE];                // packed (src, val) 8B
__device__ int   g_idx64;
__device__ int   g_blksum[128];
__device__ int   g_blkoff[128];
__device__ int   g_arrive;

// edge_index may be int64 (reference declares it) or int32 (jax x64-disabled
// canonicalization). Detected at runtime; branch on device flag.
__device__ __forceinline__ int ld_idx(const void* ei, long long pos) {
    if (g_idx64)
        return (int)((const long long*)ei)[pos];
    return ((const int*)ei)[pos];
}

// init: zero degcnt/arrive; thread 0 detects index width (odd 32-bit words of
// first 64 entries all zero iff int64, since indices < 1e5).
__global__ void k_init(const unsigned int* ei) {
    int i = blockIdx.x * blockDim.x + threadIdx.x;
    if (i < NN) g_degcnt[i] = 0ull;
    if (i == 0) {
        unsigned v = 0;
        for (int j = 0; j < 64; j++) v |= ei[2 * j + 1];
        g_idx64 = (v == 0) ? 1 : 0;
        g_arrive = 0;
    }
}

// pass 1 over edges: ONE packed 64-bit atomic per edge.
// add = (1 << 40) | round(ew * 2^25); return's high bits = rank in dst bucket.
__global__ void k_degcnt(const void* ei, const float* __restrict__ ew) {
    int e = blockIdx.x * blockDim.x + threadIdx.x;
    if (e < EE) {
        int d = ld_idx(ei, (long long)EE + e);       // dst row
        unsigned long long add =
            (1ull << CNTSHIFT) |
            (unsigned long long)(unsigned)__float2uint_rn(ew[e] * FIXSCALE);
        unsigned long long old = atomicAdd(&g_degcnt[d], add);
        g_rank[e] = (int)(old >> CNTSHIFT);
    }
}

// ---- scan phase A: shuffle block scan; ticketed last block scans block sums ----
__global__ void k_scanA() {
    __shared__ int wsum[32];
    __shared__ int sb[128];
    __shared__ int s_last;
    const int t    = threadIdx.x;
    const int lane = t & 31;
    const int warp = t >> 5;
    int i = blockIdx.x * 1024 + t;
    int v = (i < NN) ? (int)(g_degcnt[i] >> CNTSHIFT) : 0;

    int x = v;
#pragma unroll
    for (int off = 1; off < 32; off <<= 1) {
        int y = __shfl_up_sync(0xffffffff, x, off);
        if (lane >= off) x += y;
    }
    if (lane == 31) wsum[warp] = x;
    __syncthreads();
    if (warp == 0) {
        int w = (lane < 32) ? wsum[lane] : 0;
#pragma unroll
        for (int off = 1; off < 32; off <<= 1) {
            int y = __shfl_up_sync(0xffffffff, w, off);
            if (lane >= off) w += y;
        }
        wsum[lane] = w;                              // inclusive warp sums
    }
    __syncthreads();
    int incl = x + (warp ? wsum[warp - 1] : 0);
    if (i < NN) g_rowptr[i] = incl - v;              // block-local exclusive
    if (t == 1023) g_blksum[blockIdx.x] = incl;
    __threadfence();
    __syncthreads();
    if (t == 0) s_last = (atomicAdd(&g_arrive, 1) == (int)gridDim.x - 1);
    __syncthreads();
    if (s_last) {                                    // uniform branch
        int nb = (int)gridDim.x;
        int bv = (t < 128 && t < nb) ? g_blksum[t] : 0;
        if (t < 128) sb[t] = bv;
        __syncthreads();
        for (int off = 1; off < 128; off <<= 1) {
            int a = (t < 128 && t >= off) ? sb[t - off] : 0;
            __syncthreads();
            if (t < 128) sb[t] += a;
            __syncthreads();
        }
        if (t < nb) g_blkoff[t] = sb[t] - bv;        // exclusive
    }
}

__global__ void k_scanC() {
    int i = blockIdx.x * blockDim.x + threadIdx.x;
    if (i < NN) {
        g_rowptr[i] = g_rowptr[i] + g_blkoff[i >> 10];
        unsigned long long dc = g_degcnt[i];
        float deg = (float)((double)(dc & ((1ull << CNTSHIFT) - 1)) *
                            (1.0 / (double)FIXSCALE));
        g_dinv[i] = rsqrtf(1.0f + deg);              // +1 = self-loop weight
    }
    if (i == 0) g_rowptr[NN] = EE;
}

// pass 2 over edges: atomic-free placement via rowptr + rank, packed 8B store.
// stored val = dinv[src]*w  (dinv[dst] applied once per node in agg)
__global__ void k_scatter(const void* ei, const float* __restrict__ ew) {
    int e = blockIdx.x * blockDim.x + threadIdx.x;
    if (e < EE) {
        int s = ld_idx(ei, e);
        int d = ld_idx(ei, (long long)EE + e);
        int pos = g_rowptr[d] + g_rank[e];
        float v = g_dinv[s] * ew[e];
        g_edge[pos] = make_uint2((unsigned)s, __float_as_uint(v));
    }
}

// ================================ GEMM kernels ================================
#define APAD 72                               // 16-bit row stride (conflict-free frags)

// ---- GEMM1: fp32 A, bf16 hi/lo split (3 MMAs), fp16 out ----
#define SM_AHI 0
#define SM_ALO (128 * APAD)
#define SM_BHI (2 * 128 * APAD)
#define SM_BLO (2 * 128 * APAD + 64 * APAD)
#define SMEM_DYN ((2 * 128 * APAD + 2 * 64 * APAD) * 2)   // 55296 B

// ---- GEMM2/head: fp16 A exact (2 MMAs), W hi/lo split ----
#define SMF_A   0
#define SMF_BHI (128 * APAD)
#define SMF_BLO (128 * APAD + 64 * APAD)
#define SMEM_F16 ((128 * APAD + 2 * 64 * APAD) * 2)        // 36864 B
#define SMEM_HEAD 37504                                    // head stage needs 37440

__device__ __forceinline__ void mma_bf16(float* c, const uint32_t* a,
                                         uint32_t b0, uint32_t b1) {
    asm volatile(
        "mma.sync.aligned.m16n8k16.row.col.f32.bf16.bf16.f32 "
        "{%0,%1,%2,%3}, {%4,%5,%6,%7}, {%8,%9}, {%0,%1,%2,%3};"
        : "+f"(c[0]), "+f"(c[1]), "+f"(c[2]), "+f"(c[3])
        : "r"(a[0]), "r"(a[1]), "r"(a[2]), "r"(a[3]), "r"(b0), "r"(b1));
}
__device__ __forceinline__ void mma_f16(float* c, const uint32_t* a,
                                        uint32_t b0, uint32_t b1) {
    asm volatile(
        "mma.sync.aligned.m16n8k16.row.col.f32.f16.f16.f32 "
        "{%0,%1,%2,%3}, {%4,%5,%6,%7}, {%8,%9}, {%0,%1,%2,%3};"
        : "+f"(c[0]), "+f"(c[1]), "+f"(c[2]), "+f"(c[3])
        : "r"(a[0]), "r"(a[1]), "r"(a[2]), "r"(a[3]), "r"(b0), "r"(b1));
}

// bf16-split mainloop (GEMM1), fp32 A
template <int KTOT>
__device__ __forceinline__ void gemm_mainloop_bf16(
    const float* __restrict__ A, const float* __restrict__ W, int nrows,
    char* dsm, int row0, int tid, int wid, int g, int tg, float acc[2][8][4]) {
    __nv_bfloat16* Ahi = (__nv_bfloat16*)dsm + SM_AHI;
    __nv_bfloat16* Alo = (__nv_bfloat16*)dsm + SM_ALO;
    __nv_bfloat16* Bhi = (__nv_bfloat16*)dsm + SM_BHI;
    __nv_bfloat16* Blo = (__nv_bfloat16*)dsm + SM_BLO;
    const int m0 = wid * 32;

    for (int kt = 0; kt < KTOT; kt += 64) {
#pragma unroll
        for (int it = 0; it < 8; it++) {
            int chunk = it * 128 + tid;
            int r  = chunk >> 3;
            int kc = (chunk & 7) * 8;
            int row = row0 + r;
            float v[8];
            if (row < nrows) {
                const float4* p = (const float4*)(A + (size_t)row * KTOT + kt + kc);
                float4 a = p[0], b = p[1];
                v[0] = a.x; v[1] = a.y; v[2] = a.z; v[3] = a.w;
                v[4] = b.x; v[5] = b.y; v[6] = b.z; v[7] = b.w;
            } else {
#pragma unroll
                for (int j = 0; j < 8; j++) v[j] = 0.0f;
            }
#pragma unroll
            for (int j = 0; j < 4; j++) {
                __nv_bfloat162 h, l;
                h.x = __float2bfloat16(v[2 * j]);
                h.y = __float2bfloat16(v[2 * j + 1]);
                l.x = __float2bfloat16(v[2 * j]     - __bfloat162float(h.x));
                l.y = __float2bfloat16(v[2 * j + 1] - __bfloat162float(h.y));
                *(__nv_bfloat162*)&Ahi[r * APAD + kc + 2 * j] = h;
                *(__nv_bfloat162*)&Alo[r * APAD + kc + 2 * j] = l;
            }
        }
#pragma unroll
        for (int it = 0; it < 32; it++) {
            int idx = it * 128 + tid;
            int n = idx & 63, k = idx >> 6;
            float w = W[(size_t)(kt + k) * HH + n];
            __nv_bfloat16 h = __float2bfloat16(w);
            Bhi[n * APAD + k] = h;
            Blo[n * APAD + k] = __float2bfloat16(w - __bfloat162float(h));
        }
        __syncthreads();

#pragma unroll
        for (int kc = 0; kc < 64; kc += 16) {
            uint32_t ah[2][4], al[2][4];
#pragma unroll
            for (int mt = 0; mt < 2; mt++) {
                int r = m0 + mt * 16 + g;
                ah[mt][0] = *(const uint32_t*)&Ahi[r * APAD + kc + tg * 2];
                ah[mt][1] = *(const uint32_t*)&Ahi[(r + 8) * APAD + kc + tg * 2];
                ah[mt][2] = *(const uint32_t*)&Ahi[r * APAD + kc + 8 + tg * 2];
                ah[mt][3] = *(const uint32_t*)&Ahi[(r + 8) * APAD + kc + 8 + tg * 2];
                al[mt][0] = *(const uint32_t*)&Alo[r * APAD + kc + tg * 2];
                al[mt][1] = *(const uint32_t*)&Alo[(r + 8) * APAD + kc + tg * 2];
                al[mt][2] = *(const uint32_t*)&Alo[r * APAD + kc + 8 + tg * 2];
                al[mt][3] = *(const uint32_t*)&Alo[(r + 8) * APAD + kc + 8 + tg * 2];
            }
#pragma unroll
            for (int nt = 0; nt < 8; nt++) {
                int n = nt * 8 + g;
                uint32_t bh0 = *(const uint32_t*)&Bhi[n * APAD + kc + tg * 2];
                uint32_t bh1 = *(const uint32_t*)&Bhi[n * APAD + kc + 8 + tg * 2];
                uint32_t bl0 = *(const uint32_t*)&Blo[n * APAD + kc + tg * 2];
                uint32_t bl1 = *(const uint32_t*)&Blo[n * APAD + kc + 8 + tg * 2];
#pragma unroll
                for (int mt = 0; mt < 2; mt++) {
                    mma_bf16(acc[mt][nt], ah[mt], bh0, bh1);   // hi*hi
                    mma_bf16(acc[mt][nt], ah[mt], bl0, bl1);   // hi*lo
                    mma_bf16(acc[mt][nt], al[mt], bh0, bh1);   // lo*hi
                }
            }
        }
        __syncthreads();
    }
}

// fp16-exact-A mainloop (K=64): A from fp16 table, W split hi/lo (2 MMAs)
__device__ __forceinline__ void gemm_mainloop_f16(
    const uint2* __restrict__ A16, const float* __restrict__ W, int nrows,
    char* dsm, int row0, int tid, int wid, int g, int tg, float acc[2][8][4]) {
    __half* Ah  = (__half*)dsm + SMF_A;
    __half* Bhi = (__half*)dsm + SMF_BHI;
    __half* Blo = (__half*)dsm + SMF_BLO;
    const int m0 = wid * 32;

#pragma unroll
    for (int it = 0; it < 16; it++) {                // A: 128 rows x 64 fp16
        int idx = it * 128 + tid;
        int r = idx >> 4, c = idx & 15;              // c = 8B chunk (4 halfs)
        int row = row0 + r;
        uint2 v = (row < nrows) ? A16[(size_t)row * 16 + c] : make_uint2(0u, 0u);
        *(uint2*)&Ah[r * APAD + c * 4] = v;
    }
#pragma unroll
    for (int it = 0; it < 32; it++) {                // B: W[k][n] -> Bs[n][k]
        int idx = it * 128 + tid;
        int n = idx & 63, k = idx >> 6;
        float w = W[(size_t)k * HH + n];
        __half h = __float2half_rn(w);
        Bhi[n * APAD + k] = h;
        Blo[n * APAD + k] = __float2half_rn(w - __half2float(h));
    }
    __syncthreads();

#pragma unroll
    for (int kc = 0; kc < 64; kc += 16) {
        uint32_t a[2][4];
#pragma unroll
        for (int mt = 0; mt < 2; mt++) {
            int r = m0 + mt * 16 + g;
            a[mt][0] = *(const uint32_t*)&Ah[r * APAD + kc + tg * 2];
            a[mt][1] = *(const uint32_t*)&Ah[(r + 8) * APAD + kc + tg * 2];
            a[mt][2] = *(const uint32_t*)&Ah[r * APAD + kc + 8 + tg * 2];
            a[mt][3] = *(const uint32_t*)&Ah[(r + 8) * APAD + kc + 8 + tg * 2];
        }
#pragma unroll
        for (int nt = 0; nt < 8; nt++) {
            int n = nt * 8 + g;
            uint32_t bh0 = *(const uint32_t*)&Bhi[n * APAD + kc + tg * 2];
            uint32_t bh1 = *(const uint32_t*)&Bhi[n * APAD + kc + 8 + tg * 2];
            uint32_t bl0 = *(const uint32_t*)&Blo[n * APAD + kc + tg * 2];
            uint32_t bl1 = *(const uint32_t*)&Blo[n * APAD + kc + 8 + tg * 2];
#pragma unroll
            for (int mt = 0; mt < 2; mt++) {
                mma_f16(acc[mt][nt], a[mt], bh0, bh1);   // A*Whi
                mma_f16(acc[mt][nt], a[mt], bl0, bl1);   // A*Wlo
            }
        }
    }
    __syncthreads();                                 // smem reusable after this
}

// fp16 epilogue writer (h layout: row * 32 half2, feature-linear)
__device__ __forceinline__ void write_h16(__half2* out, int nrows, int row0,
                                          int wid, int g, int tg, float acc[2][8][4]) {
#pragma unroll
    for (int mt = 0; mt < 2; mt++) {
        int r0 = row0 + wid * 32 + mt * 16 + g;
        int r1 = r0 + 8;
#pragma unroll
        for (int nt = 0; nt < 8; nt++) {
            int h2c = nt * 4 + tg;
            if (r0 < nrows)
                out[(size_t)r0 * 32 + h2c] = __floats2half2_rn(acc[mt][nt][0], acc[mt][nt][1]);
            if (r1 < nrows)
                out[(size_t)r1 * 32 + h2c] = __floats2half2_rn(acc[mt][nt][2], acc[mt][nt][3]);
        }
    }
}

// GEMM1: x(fp32) @ W1 -> fp16 h
template <int KTOT>
__global__ void __launch_bounds__(128)
gemm_tc(const float* __restrict__ A, const float* __restrict__ W,
        __half2* __restrict__ out, int nrows) {
    extern __shared__ char dsm[];
    const int tid = threadIdx.x, wid = tid >> 5, lane = tid & 31;
    const int g = lane >> 2, tg = lane & 3;
    const int row0 = blockIdx.x * 128;
    float acc[2][8][4];
#pragma unroll
    for (int mt = 0; mt < 2; mt++)
#pragma unroll
        for (int nt = 0; nt < 8; nt++)
#pragma unroll
            for (int j = 0; j < 4; j++) acc[mt][nt][j] = 0.0f;
    gemm_mainloop_bf16<KTOT>(A, W, nrows, dsm, row0, tid, wid, g, tg, acc);
    write_h16(out, nrows, row0, wid, g, tg, acc);
}

// GEMM2: h(fp16) @ W2 -> fp16 h  (row_base for stream-pipelined halves)
__global__ void __launch_bounds__(128)
gemm_f16(const uint2* __restrict__ A16, const float* __restrict__ W,
         __half2* __restrict__ out, int nrows, int row_base) {
    extern __shared__ char dsm[];
    const int tid = threadIdx.x, wid = tid >> 5, lane = tid & 31;
    const int g = lane >> 2, tg = lane & 3;
    const int row0 = row_base + blockIdx.x * 128;
    float acc[2][8][4];
#pragma unroll
    for (int mt = 0; mt < 2; mt++)
#pragma unroll
        for (int nt = 0; nt < 8; nt++)
#pragma unroll
            for (int j = 0; j < 4; j++) acc[mt][nt][j] = 0.0f;
    gemm_mainloop_f16(A16, W, nrows, dsm, row0, tid, wid, g, tg, acc);
    write_h16(out, nrows, row0, wid, g, tg, acc);
}

// GEMM3 (fp16 A) + bias/relu + fused MLP head (logits @ Wm2 + bm2, softmax)
__global__ void __launch_bounds__(128)
gemm_head(const uint2* __restrict__ A16, const float* __restrict__ Wm1,
          const float* __restrict__ bm1, const float* __restrict__ Wm2,
          const float* __restrict__ bm2, float* __restrict__ out, int nrows,
          int row_base) {
    extern __shared__ char dsm[];
    const int tid = threadIdx.x, wid = tid >> 5, lane = tid & 31;
    const int g = lane >> 2, tg = lane & 3;
    const int row0 = row_base + blockIdx.x * 128;
    float acc[2][8][4];
#pragma unroll
    for (int mt = 0; mt < 2; mt++)
#pragma unroll
        for (int nt = 0; nt < 8; nt++)
#pragma unroll
            for (int j = 0; j < 4; j++) acc[mt][nt][j] = 0.0f;
    gemm_mainloop_f16(A16, Wm1, nrows, dsm, row0, tid, wid, g, tg, acc);

    // stage relu(acc + bm1) into smem [128][65] (tile memory dead after mainloop)
    float* st  = (float*)dsm;                 // 33280 B
    float* sW  = st + 128 * 65;               // 4096 B
    float* sbv = sW + 64 * 16;                // 64 B  (total 37440 <= SMEM_HEAD)
#pragma unroll
    for (int mt = 0; mt < 2; mt++) {
        int rl0 = wid * 32 + mt * 16 + g;
#pragma unroll
        for (int nt = 0; nt < 8; nt++) {
            int c = nt * 8 + tg * 2;
            float b0 = __ldg(&bm1[c]), b1 = __ldg(&bm1[c + 1]);
            st[rl0 * 65 + c]           = fmaxf(acc[mt][nt][0] + b0, 0.0f);
            st[rl0 * 65 + c + 1]       = fmaxf(acc[mt][nt][1] + b1, 0.0f);
            st[(rl0 + 8) * 65 + c]     = fmaxf(acc[mt][nt][2] + b0, 0.0f);
            st[(rl0 + 8) * 65 + c + 1] = fmaxf(acc[mt][nt][3] + b1, 0.0f);
        }
    }
    for (int i = tid; i < HH * CC; i += 128) sW[i] = Wm2[i];
    if (tid < CC) sbv[tid] = bm2[tid];
    __syncthreads();

    int r = row0 + tid;                       // one row per thread
    if (r < nrows) {
        float lg[CC];
#pragma unroll
        for (int c = 0; c < CC; c++) lg[c] = sbv[c];
        const float* mrow = st + tid * 65;    // stride 65 -> conflict-free
#pragma unroll
        for (int k = 0; k < HH; k++) {
            float av = mrow[k];
#pragma unroll
            for (int c = 0; c < CC; c++) lg[c] += av * sW[k * CC + c];
        }
        float mx = lg[0];
#pragma unroll
        for (int c = 1; c < CC; c++) mx = fmaxf(mx, lg[c]);
        float ssum = 0.0f;
#pragma unroll
        for (int c = 0; c < CC; c++) { lg[c] = __expf(lg[c] - mx); ssum += lg[c]; }
        float inv = 1.0f / ssum;
        float4* op = (float4*)(out + (size_t)r * CC);
#pragma unroll
        for (int c4 = 0; c4 < 4; c4++)
            op[c4] = make_float4(lg[c4 * 4] * inv, lg[c4 * 4 + 1] * inv,
                                 lg[c4 * 4 + 2] * inv, lg[c4 * 4 + 3] * inv);
    }
}

// ---- edge aggregation: QUARTER-WARP per node (8 lanes x 16B = 128B/row) ----
// out[i] = relu( dinv[i] * ( dinv[i]*h[i] + sum_e val'[e]*h[col[e]] ) + bias )
__device__ __forceinline__ void acc8(uint4 p, float v, float* a) {
    float2 q;
    q = __half22float2(*(const __half2*)&p.x); a[0] += v * q.x; a[1] += v * q.y;
    q = __half22float2(*(const __half2*)&p.y); a[2] += v * q.x; a[3] += v * q.y;
    q = __half22float2(*(const __half2*)&p.z); a[4] += v * q.x; a[5] += v * q.y;
    q = __half22float2(*(const __half2*)&p.w); a[6] += v * q.x; a[7] += v * q.y;
}

__global__ void k_agg8(const uint4* __restrict__ hp, const float* __restrict__ bias,
                       uint4* __restrict__ out, int node_base) {
    int gt = blockIdx.x * blockDim.x + threadIdx.x;
    int w  = node_base + (gt >> 3);            // node = quarter-warp
    int l  = gt & 7;                           // lane: feats 8l..8l+7
    if (w >= NN) return;
    float di = g_dinv[w];

    float a[8];
    {
        uint4 hv = hp[(size_t)w * 8 + l];
        float2 q;
        q = __half22float2(*(const __half2*)&hv.x); a[0] = di * q.x; a[1] = di * q.y;
        q = __half22float2(*(const __half2*)&hv.y); a[2] = di * q.x; a[3] = di * q.y;
        q = __half22float2(*(const __half2*)&hv.z); a[4] = di * q.x; a[5] = di * q.y;
        q = __half22float2(*(const __half2*)&hv.w); a[6] = di * q.x; a[7] = di * q.y;
    }

    int e  = __ldg(&g_rowptr[w]);
    int e1 = __ldg(&g_rowptr[w + 1]);
    for (; e + 4 <= e1; e += 4) {
        uint2 ev0 = g_edge[e],     ev1 = g_edge[e + 1];
        uint2 ev2 = g_edge[e + 2], ev3 = g_edge[e + 3];
        uint4 p0 = hp[(size_t)ev0.x * 8 + l];
        uint4 p1 = hp[(size_t)ev1.x * 8 + l];
        uint4 p2 = hp[(size_t)ev2.x * 8 + l];
        uint4 p3 = hp[(size_t)ev3.x * 8 + l];
        acc8(p0, __uint_as_float(ev0.y), a);
        acc8(p1, __uint_as_float(ev1.y), a);
        acc8(p2, __uint_as_float(ev2.y), a);
        acc8(p3, __uint_as_float(ev3.y), a);
    }
    for (; e < e1; e++) {
        uint2 ev = g_edge[e];
        uint4 p  = hp[(size_t)ev.x * 8 + l];
        acc8(p, __uint_as_float(ev.y), a);
    }

    float4 b0 = *(const float4*)&bias[8 * l];
    float4 b1 = *(const float4*)&bias[8 * l + 4];
    __half2 o0 = __floats2half2_rn(fmaxf(di * a[0] + b0.x, 0.0f),
                                   fmaxf(di * a[1] + b0.y, 0.0f));
    __half2 o1 = __floats2half2_rn(fmaxf(di * a[2] + b0.z, 0.0f),
                                   fmaxf(di * a[3] + b0.w, 0.0f));
    __half2 o2 = __floats2half2_rn(fmaxf(di * a[4] + b1.x, 0.0f),
                                   fmaxf(di * a[5] + b1.y, 0.0f));
    __half2 o3 = __floats2half2_rn(fmaxf(di * a[6] + b1.z, 0.0f),
                                   fmaxf(di * a[7] + b1.w, 0.0f));
    uint4 o;
    o.x = *(uint32_t*)&o0; o.y = *(uint32_t*)&o1;
    o.z = *(uint32_t*)&o2; o.w = *(uint32_t*)&o3;
    out[(size_t)w * 8 + l] = o;
}

// ---------------- launch ----------------
extern "C" void kernel_launch(void* const* d_in, const int* in_sizes, int n_in,
                              void* d_out, int out_size) {
    const float* x   = (const float*)d_in[0];
    const void*  ei  = d_in[1];
    const float* ew  = (const float*)d_in[2];
    const float* W1  = (const float*)d_in[3];
    const float* b1  = (const float*)d_in[4];
    const float* W2  = (const float*)d_in[5];
    const float* b2  = (const float*)d_in[6];
    const float* Wm1 = (const float*)d_in[7];
    const float* bm1 = (const float*)d_in[8];
    const float* Wm2 = (const float*)d_in[9];
    const float* bm2 = (const float*)d_in[10];
    float* out = (float*)d_out;

    float *pA, *pB;
    cudaGetSymbolAddress((void**)&pA, g_bufA);
    cudaGetSymbolAddress((void**)&pB, g_bufB);
    // triple fp16 buffers: hA = bufA lo half, hB = bufB, hC = bufA hi half
    __half2* hA = (__half2*)pA;
    __half2* hB = (__half2*)pB;
    __half2* hC = (__half2*)(pA + (size_t)NN * 32);  // +12.8 MB

    static cudaStream_t s2 = 0;
    static cudaEvent_t evA = 0, evB = 0, evCsr = 0, evG = 0, evC = 0, evD = 0;
    if (!s2) {
        cudaStreamCreateWithFlags(&s2, cudaStreamNonBlocking);
        cudaEventCreateWithFlags(&evA,   cudaEventDisableTiming);
        cudaEventCreateWithFlags(&evB,   cudaEventDisableTiming);
        cudaEventCreateWithFlags(&evCsr, cudaEventDisableTiming);
        cudaEventCreateWithFlags(&evG,   cudaEventDisableTiming);
        cudaEventCreateWithFlags(&evC,   cudaEventDisableTiming);
        cudaEventCreateWithFlags(&evD,   cudaEventDisableTiming);
        cudaFuncSetAttribute(gemm_tc<INF>, cudaFuncAttributeMaxDynamicSharedMemorySize, SMEM_DYN);
        cudaFuncSetAttribute(gemm_f16,     cudaFuncAttributeMaxDynamicSharedMemorySize, SMEM_F16);
        cudaFuncSetAttribute(gemm_head,    cudaFuncAttributeMaxDynamicSharedMemorySize, SMEM_HEAD);
    }

    const int gemm_grid = (NN + 127) / 128;          // 782
    const int nblk      = (NN + 1023) / 1024;        // 98

    // half splits (row-local GEMMs allow agg->gemm pipelining per half)
    const int glo = ROWSPLIT / 128;                          // 391
    const int ghi = gemm_grid - glo;                         // 391
    const int alo = (ROWSPLIT * 8) / 256;                    // 1564
    const int ahi = ((NN - ROWSPLIT) * 8 + 255) / 256;       // 1561

    // fork: GEMM1 (x @ W1 -> hA) alongside CSR build
    cudaEventRecord(evA, 0);
    cudaStreamWaitEvent(s2, evA, 0);
    gemm_tc<INF><<<gemm_grid, 128, SMEM_DYN, s2>>>(x, W1, hA, NN);
    cudaEventRecord(evB, s2);

    // CSR build on main stream (single packed atomic per edge in pass 1)
    k_init<<<(NN + 255) / 256, 256>>>((const unsigned int*)ei);
    k_degcnt<<<(EE + 255) / 256, 256>>>(ei, ew);
    k_scanA<<<nblk, 1024>>>();
    k_scanC<<<(NN + 255) / 256, 256>>>();
    k_scatter<<<(EE + 255) / 256, 256>>>(ei, ew);
    cudaEventRecord(evCsr, 0);

    cudaStreamWaitEvent(0,  evB,   0);               // stream0 joins GEMM1
    cudaStreamWaitEvent(s2, evCsr, 0);               // s2 joins CSR (already has GEMM1)

    // --- pipelined stage 1: agg1(hA->hB) then gemm2(hB->hC), per half ---
    // gemm2 writes hC (disjoint from hA) so the other stream's agg1 gather is safe.
    k_agg8<<<alo, 256, 0, 0>>>((const uint4*)hA, b1, (uint4*)hB, 0);
    gemm_f16<<<glo, 128, SMEM_F16, 0>>>((const uint2*)hB, W2, hC, NN, 0);
    cudaEventRecord(evG, 0);

    k_agg8<<<ahi, 256, 0, s2>>>((const uint4*)hA, b1, (uint4*)hB, ROWSPLIT);
    gemm_f16<<<ghi, 128, SMEM_F16, s2>>>((const uint2*)hB, W2, hC, NN, ROWSPLIT);
    cudaEventRecord(evC, s2);

    // agg2 gathers ALL of hC: full join both ways
    cudaStreamWaitEvent(0,  evC, 0);
    cudaStreamWaitEvent(s2, evG, 0);

    // --- pipelined stage 2: agg2(hC->hB) then head(hB->out), per half ---
    // head writes `out` (disjoint from hC) so the other stream's agg2 gather is safe.
    k_agg8<<<alo, 256, 0, 0>>>((const uint4*)hC, b2, (uint4*)hB, 0);
    gemm_head<<<glo, 128, SMEM_HEAD, 0>>>((const uint2*)hB, Wm1, bm1, Wm2, bm2,
                                          out, NN, 0);

    k_agg8<<<ahi, 256, 0, s2>>>((const uint4*)hC, b2, (uint4*)hB, ROWSPLIT);
    gemm_head<<<ghi, 128, SMEM_HEAD, s2>>>((const uint2*)hB, Wm1, bm1, Wm2, bm2,
                                           out, NN, ROWSPLIT);
    cudaEventRecord(evD, s2);
    cudaStreamWaitEvent(0, evD, 0);                  // join for graph end
}